// round 6
// baseline (speedup 1.0000x reference)
#include <cuda_runtime.h>
#include <math.h>

// Problem constants
#define B_ 2
#define S_ 2048
#define D_ 1024
#define H_ 16
#define DEPTH_ 64
#define M_ (B_ * S_)            // 4096
#define BH_ (B_ * H_)           // 32
#define OUT_ELEMS (B_ * S_ * D_)
#define ATTN_ELEMS ((size_t)BH_ * S_ * S_)

// Scratch
__device__ float g_Qh[(size_t)BH_ * S_ * DEPTH_];
__device__ float g_Kh[(size_t)BH_ * S_ * DEPTH_];
__device__ float g_Vh[(size_t)BH_ * S_ * DEPTH_];
__device__ float g_ctx[(size_t)M_ * D_];
__device__ float g_attn_scratch[ATTN_ELEMS];

// ---------------------------------------------------------------------------
// tf32 helpers
// ---------------------------------------------------------------------------
__device__ __forceinline__ float f2tf(float x) {
    unsigned r; asm("cvt.rna.tf32.f32 %0, %1;" : "=r"(r) : "f"(x));
    return __uint_as_float(r);
}
__device__ __forceinline__ void mma_tf32(
    float& c0, float& c1, float& c2, float& c3,
    unsigned a0, unsigned a1, unsigned a2, unsigned a3,
    unsigned b0, unsigned b1)
{
    asm volatile(
        "mma.sync.aligned.m16n8k8.row.col.f32.tf32.tf32.f32 "
        "{%0,%1,%2,%3}, {%4,%5,%6,%7}, {%8,%9}, {%0,%1,%2,%3};"
        : "+f"(c0), "+f"(c1), "+f"(c2), "+f"(c3)
        : "r"(a0), "r"(a1), "r"(a2), "r"(a3), "r"(b0), "r"(b1));
}
#define U(x) __float_as_uint(x)

// k-permutation within 8-groups: position (k&3)*2 + (k>>2 & 1) holds k.
// A float2 at even position 2t then yields (k=t, k=t+4) = exactly the
// (a0,a2) / (b0,b1) register pair of an m16n8k8 tf32 fragment.
__device__ __forceinline__ int perm8(int c) {
    return (c & ~7) | ((c & 3) << 1) | ((c & 4) >> 2);
}

// ---------------------------------------------------------------------------
// Projection GEMM body: P = X @ W + b. X:[4096,1024] W:[1024,1024]
// CTA 128x128, BK=16 double-buffered, 8 warps (2m x 4n), warp 64x32.
// Smem rows padded to 24 (24 mod 32 = 24: conflict-free for frag pattern).
// ---------------------------------------------------------------------------
__device__ __forceinline__ void proj_body(
    const float* __restrict__ X, const float* __restrict__ W,
    const float* __restrict__ bias, float* __restrict__ out, int headsplit)
{
    __shared__ float As[2][128][24];
    __shared__ float Bs[2][128][24];
    const int tid = threadIdx.x, lane = tid & 31, wid = tid >> 5;
    const int wm = wid & 1, wn = wid >> 1;
    const int row0 = blockIdx.y * 128, col0 = blockIdx.x * 128;

    const int far = tid >> 2, fac = (tid & 3) * 4;   // A rows far, far+64
    const int fwk = tid >> 5, fwn = (tid & 31) * 4;  // W k-rows fwk, fwk+8

    float acc[4][4][4];
#pragma unroll
    for (int mi = 0; mi < 4; mi++)
#pragma unroll
        for (int ni = 0; ni < 4; ni++)
#pragma unroll
            for (int t = 0; t < 4; t++) acc[mi][ni][t] = 0.f;

    float4 pa0, pa1, pw0, pw1;
    pa0 = *(const float4*)(X + (size_t)(row0 + far) * D_ + fac);
    pa1 = *(const float4*)(X + (size_t)(row0 + far + 64) * D_ + fac);
    pw0 = *(const float4*)(W + (size_t)fwk * D_ + col0 + fwn);
    pw1 = *(const float4*)(W + (size_t)(fwk + 8) * D_ + col0 + fwn);
    {
        As[0][far][perm8(fac + 0)] = f2tf(pa0.x);
        As[0][far][perm8(fac + 1)] = f2tf(pa0.y);
        As[0][far][perm8(fac + 2)] = f2tf(pa0.z);
        As[0][far][perm8(fac + 3)] = f2tf(pa0.w);
        As[0][far + 64][perm8(fac + 0)] = f2tf(pa1.x);
        As[0][far + 64][perm8(fac + 1)] = f2tf(pa1.y);
        As[0][far + 64][perm8(fac + 2)] = f2tf(pa1.z);
        As[0][far + 64][perm8(fac + 3)] = f2tf(pa1.w);
        int pk0 = perm8(fwk), pk1 = perm8(fwk + 8);
        Bs[0][fwn + 0][pk0] = f2tf(pw0.x); Bs[0][fwn + 1][pk0] = f2tf(pw0.y);
        Bs[0][fwn + 2][pk0] = f2tf(pw0.z); Bs[0][fwn + 3][pk0] = f2tf(pw0.w);
        Bs[0][fwn + 0][pk1] = f2tf(pw1.x); Bs[0][fwn + 1][pk1] = f2tf(pw1.y);
        Bs[0][fwn + 2][pk1] = f2tf(pw1.z); Bs[0][fwn + 3][pk1] = f2tf(pw1.w);
    }
    __syncthreads();

    const int nc = D_ / 16;   // 64
    for (int c = 0; c < nc; c++) {
        const int cur = c & 1;
        if (c + 1 < nc) {
            const int k0 = (c + 1) * 16;
            pa0 = *(const float4*)(X + (size_t)(row0 + far) * D_ + k0 + fac);
            pa1 = *(const float4*)(X + (size_t)(row0 + far + 64) * D_ + k0 + fac);
            pw0 = *(const float4*)(W + (size_t)(k0 + fwk) * D_ + col0 + fwn);
            pw1 = *(const float4*)(W + (size_t)(k0 + fwk + 8) * D_ + col0 + fwn);
        }
#pragma unroll
        for (int ks = 0; ks < 2; ks++) {
            unsigned af[4][4], bf[4][2];
            const int kp = ks * 8 + (lane & 3) * 2;
#pragma unroll
            for (int mi = 0; mi < 4; mi++) {
                int r = wm * 64 + mi * 16 + (lane >> 2);
                float2 lo = *(const float2*)&As[cur][r][kp];
                float2 hi = *(const float2*)&As[cur][r + 8][kp];
                af[mi][0] = U(lo.x); af[mi][1] = U(hi.x);
                af[mi][2] = U(lo.y); af[mi][3] = U(hi.y);
            }
#pragma unroll
            for (int ni = 0; ni < 4; ni++) {
                int r = wn * 32 + ni * 8 + (lane >> 2);
                float2 bb = *(const float2*)&Bs[cur][r][kp];
                bf[ni][0] = U(bb.x); bf[ni][1] = U(bb.y);
            }
#pragma unroll
            for (int mi = 0; mi < 4; mi++)
#pragma unroll
                for (int ni = 0; ni < 4; ni++)
                    mma_tf32(acc[mi][ni][0], acc[mi][ni][1], acc[mi][ni][2], acc[mi][ni][3],
                             af[mi][0], af[mi][1], af[mi][2], af[mi][3],
                             bf[ni][0], bf[ni][1]);
        }
        if (c + 1 < nc) {
            const int nxt = 1 - cur;
            As[nxt][far][perm8(fac + 0)] = f2tf(pa0.x);
            As[nxt][far][perm8(fac + 1)] = f2tf(pa0.y);
            As[nxt][far][perm8(fac + 2)] = f2tf(pa0.z);
            As[nxt][far][perm8(fac + 3)] = f2tf(pa0.w);
            As[nxt][far + 64][perm8(fac + 0)] = f2tf(pa1.x);
            As[nxt][far + 64][perm8(fac + 1)] = f2tf(pa1.y);
            As[nxt][far + 64][perm8(fac + 2)] = f2tf(pa1.z);
            As[nxt][far + 64][perm8(fac + 3)] = f2tf(pa1.w);
            int pk0 = perm8(fwk), pk1 = perm8(fwk + 8);
            Bs[nxt][fwn + 0][pk0] = f2tf(pw0.x); Bs[nxt][fwn + 1][pk0] = f2tf(pw0.y);
            Bs[nxt][fwn + 2][pk0] = f2tf(pw0.z); Bs[nxt][fwn + 3][pk0] = f2tf(pw0.w);
            Bs[nxt][fwn + 0][pk1] = f2tf(pw1.x); Bs[nxt][fwn + 1][pk1] = f2tf(pw1.y);
            Bs[nxt][fwn + 2][pk1] = f2tf(pw1.z); Bs[nxt][fwn + 3][pk1] = f2tf(pw1.w);
        }
        __syncthreads();
    }

#pragma unroll
    for (int mi = 0; mi < 4; mi++) {
#pragma unroll
        for (int ni = 0; ni < 4; ni++) {
            int r = row0 + wm * 64 + mi * 16 + (lane >> 2);
            int cc = col0 + wn * 32 + ni * 8 + (lane & 3) * 2;
            float2 bb = *(const float2*)(bias + cc);
            float2 v0 = make_float2(acc[mi][ni][0] + bb.x, acc[mi][ni][1] + bb.y);
            float2 v1 = make_float2(acc[mi][ni][2] + bb.x, acc[mi][ni][3] + bb.y);
            if (headsplit) {
                int b = r >> 11, s = r & 2047;
                int h = cc >> 6, d = cc & 63;
                float* dst = out + ((size_t)(b * H_ + h) * S_ + s) * DEPTH_ + d;
                *(float2*)dst = v0;
                *(float2*)(dst + 8 * DEPTH_) = v1;
            } else {
                float* dst = out + (size_t)r * D_ + cc;
                *(float2*)dst = v0;
                *(float2*)(dst + 8 * D_) = v1;
            }
        }
    }
}

// Merged Q/K/V projection: grid.z selects which projection this CTA does.
__global__ __launch_bounds__(256, 2) void qkv_kernel(
    const float* __restrict__ q, const float* __restrict__ k, const float* __restrict__ v,
    const float* __restrict__ wq, const float* __restrict__ wk, const float* __restrict__ wv,
    const float* __restrict__ bq, const float* __restrict__ bk, const float* __restrict__ bv,
    float* __restrict__ Qh, float* __restrict__ Kh, float* __restrict__ Vh)
{
    const int z = blockIdx.z;
    const float* X = (z == 0) ? q : (z == 1) ? k : v;
    const float* W = (z == 0) ? wq : (z == 1) ? wk : wv;
    const float* bias = (z == 0) ? bq : (z == 1) ? bk : bv;
    float* out = (z == 0) ? Qh : (z == 1) ? Kh : Vh;
    proj_body(X, W, bias, out, 1);
}

__global__ __launch_bounds__(256, 2) void out_proj_kernel(
    const float* __restrict__ X, const float* __restrict__ W,
    const float* __restrict__ bias, float* __restrict__ out)
{
    proj_body(X, W, bias, out, 0);
}

// ---------------------------------------------------------------------------
// Logits: per bh: C = Qh[S,64] @ Kh[S,64]^T * 0.125 + mask*1e-9
// CTA 128x128, K=64 staged once (rows padded to 72). 8 warps (2m x 4n).
// Epilogue staged through smem (stride 136) for coalesced LDG/STG.128.
// Dynamic smem: 2*128*72 floats = 73728 B.
// ---------------------------------------------------------------------------
__global__ __launch_bounds__(256, 2) void logits_kernel(
    const float* __restrict__ Qh, const float* __restrict__ Kh,
    const float* __restrict__ mask, float* __restrict__ attn)
{
    extern __shared__ float sm[];
    float* As = sm;                 // [128][72]
    float* Bs = sm + 128 * 72;      // [128][72]

    const int bh = blockIdx.z;
    const float* A = Qh + (size_t)bh * S_ * DEPTH_;
    const float* Bm = Kh + (size_t)bh * S_ * DEPTH_;
    float* C = attn + (size_t)bh * S_ * S_;
    const int bidx = bh >> 4;

    const int tid = threadIdx.x, lane = tid & 31, wid = tid >> 5;
    const int wm = wid & 1, wn = wid >> 1;
    const int row0 = blockIdx.y * 128, col0 = blockIdx.x * 128;

#pragma unroll
    for (int t = 0; t < 8; t++) {
        int idx = tid + t * 256;
        int r = idx >> 4, c0 = (idx & 15) * 4;
        float4 x = *(const float4*)(A + (size_t)(row0 + r) * DEPTH_ + c0);
        As[r * 72 + perm8(c0 + 0)] = f2tf(x.x);
        As[r * 72 + perm8(c0 + 1)] = f2tf(x.y);
        As[r * 72 + perm8(c0 + 2)] = f2tf(x.z);
        As[r * 72 + perm8(c0 + 3)] = f2tf(x.w);
        float4 y = *(const float4*)(Bm + (size_t)(col0 + r) * DEPTH_ + c0);
        Bs[r * 72 + perm8(c0 + 0)] = f2tf(y.x);
        Bs[r * 72 + perm8(c0 + 1)] = f2tf(y.y);
        Bs[r * 72 + perm8(c0 + 2)] = f2tf(y.z);
        Bs[r * 72 + perm8(c0 + 3)] = f2tf(y.w);
    }
    __syncthreads();

    float acc[4][4][4];
#pragma unroll
    for (int mi = 0; mi < 4; mi++)
#pragma unroll
        for (int ni = 0; ni < 4; ni++)
#pragma unroll
            for (int t = 0; t < 4; t++) acc[mi][ni][t] = 0.f;

#pragma unroll
    for (int ks = 0; ks < 8; ks++) {
        unsigned af[4][4], bf[4][2];
        const int kp = ks * 8 + (lane & 3) * 2;
#pragma unroll
        for (int mi = 0; mi < 4; mi++) {
            int r = wm * 64 + mi * 16 + (lane >> 2);
            float2 lo = *(const float2*)&As[r * 72 + kp];
            float2 hi = *(const float2*)&As[(r + 8) * 72 + kp];
            af[mi][0] = U(lo.x); af[mi][1] = U(hi.x);
            af[mi][2] = U(lo.y); af[mi][3] = U(hi.y);
        }
#pragma unroll
        for (int ni = 0; ni < 4; ni++) {
            int r = wn * 32 + ni * 8 + (lane >> 2);
            float2 bb = *(const float2*)&Bs[r * 72 + kp];
            bf[ni][0] = U(bb.x); bf[ni][1] = U(bb.y);
        }
#pragma unroll
        for (int mi = 0; mi < 4; mi++)
#pragma unroll
            for (int ni = 0; ni < 4; ni++)
                mma_tf32(acc[mi][ni][0], acc[mi][ni][1], acc[mi][ni][2], acc[mi][ni][3],
                         af[mi][0], af[mi][1], af[mi][2], af[mi][3],
                         bf[ni][0], bf[ni][1]);
    }

    // Stage scaled tile into smem (stride 136: conflict-free STS.64 pattern)
    __syncthreads();
    float* Cs = sm;                 // [128][136] = 17408 floats < 18432 avail
#pragma unroll
    for (int mi = 0; mi < 4; mi++) {
#pragma unroll
        for (int ni = 0; ni < 4; ni++) {
            int r = wm * 64 + mi * 16 + (lane >> 2);
            int cc = wn * 32 + ni * 8 + (lane & 3) * 2;
            *(float2*)&Cs[r * 136 + cc] =
                make_float2(acc[mi][ni][0] * 0.125f, acc[mi][ni][1] * 0.125f);
            *(float2*)&Cs[(r + 8) * 136 + cc] =
                make_float2(acc[mi][ni][2] * 0.125f, acc[mi][ni][3] * 0.125f);
        }
    }
    __syncthreads();

    // Coalesced flush: LDS.128 + LDG.128(mask) + STG.128, 16 independent iters
#pragma unroll
    for (int t = 0; t < 16; t++) {
        int idx = tid + t * 256;
        int r = idx >> 5, c4 = (idx & 31) * 4;
        float4 val = *(const float4*)&Cs[r * 136 + c4];
        float4 mk = *(const float4*)(mask + ((size_t)bidx * S_ + row0 + r) * S_ + col0 + c4);
        val.x += mk.x * 1e-9f; val.y += mk.y * 1e-9f;
        val.z += mk.z * 1e-9f; val.w += mk.w * 1e-9f;
        *(float4*)(C + (size_t)(row0 + r) * S_ + col0 + c4) = val;
    }
}

// ---------------------------------------------------------------------------
// Row softmax over 2048 elements, in place.
// ---------------------------------------------------------------------------
__global__ __launch_bounds__(256) void softmax_kernel(float* __restrict__ attn)
{
    float4* p = (float4*)(attn + (size_t)blockIdx.x * S_);
    const int tid = threadIdx.x;
    const int lane = tid & 31, warp = tid >> 5;
    __shared__ float red[8];

    float4 v0 = p[tid];
    float4 v1 = p[tid + 256];

    float m = fmaxf(fmaxf(fmaxf(v0.x, v0.y), fmaxf(v0.z, v0.w)),
                    fmaxf(fmaxf(v1.x, v1.y), fmaxf(v1.z, v1.w)));
#pragma unroll
    for (int s = 16; s > 0; s >>= 1) m = fmaxf(m, __shfl_xor_sync(~0u, m, s));
    if (lane == 0) red[warp] = m;
    __syncthreads();
    m = red[lane & 7];
#pragma unroll
    for (int s = 4; s > 0; s >>= 1) m = fmaxf(m, __shfl_xor_sync(~0u, m, s));

    v0.x = __expf(v0.x - m); v0.y = __expf(v0.y - m);
    v0.z = __expf(v0.z - m); v0.w = __expf(v0.w - m);
    v1.x = __expf(v1.x - m); v1.y = __expf(v1.y - m);
    v1.z = __expf(v1.z - m); v1.w = __expf(v1.w - m);

    float sum = (v0.x + v0.y) + (v0.z + v0.w) + (v1.x + v1.y) + (v1.z + v1.w);
#pragma unroll
    for (int s = 16; s > 0; s >>= 1) sum += __shfl_xor_sync(~0u, sum, s);
    __syncthreads();
    if (lane == 0) red[warp] = sum;
    __syncthreads();
    sum = red[lane & 7];
#pragma unroll
    for (int s = 4; s > 0; s >>= 1) sum += __shfl_xor_sync(~0u, sum, s);

    float inv = 1.f / sum;
    v0.x *= inv; v0.y *= inv; v0.z *= inv; v0.w *= inv;
    v1.x *= inv; v1.y *= inv; v1.z *= inv; v1.w *= inv;
    p[tid] = v0;
    p[tid + 256] = v1;
}

// ---------------------------------------------------------------------------
// ctx = attn[S,S] @ Vh[S,64]; merged-head output [B*S, 1024].
// CTA 128m x 64n, BK=32 double-buffered (rows padded to 40). 8 warps (4m x 2n).
// Smem-staged epilogue (stride 72). Dynamic smem: (2*128+2*64)*40 = 61440 B.
// ---------------------------------------------------------------------------
__global__ __launch_bounds__(256, 2) void ctx_kernel(
    const float* __restrict__ attn, const float* __restrict__ Vh,
    float* __restrict__ ctx)
{
    extern __shared__ float sm[];
    float* As = sm;                          // [2][128][40]
    float* Bs = sm + 2 * 128 * 40;           // [2][64][40]

    const int bh = blockIdx.y;
    const float* A = attn + (size_t)bh * S_ * S_;
    const float* Bm = Vh + (size_t)bh * S_ * DEPTH_;
    const int b = bh >> 4, h = bh & 15;

    const int tid = threadIdx.x, lane = tid & 31, wid = tid >> 5;
    const int wm = wid & 3, wn = wid >> 2;
    const int row0 = blockIdx.x * 128;

    float acc[2][4][4];
#pragma unroll
    for (int mi = 0; mi < 2; mi++)
#pragma unroll
        for (int ni = 0; ni < 4; ni++)
#pragma unroll
            for (int t = 0; t < 4; t++) acc[mi][ni][t] = 0.f;

    float4 pa[4], pv[2];
#pragma unroll
    for (int t = 0; t < 4; t++) {
        int idx = tid + t * 256;
        int r = idx >> 3, c0 = (idx & 7) * 4;
        pa[t] = *(const float4*)(A + (size_t)(row0 + r) * S_ + c0);
    }
#pragma unroll
    for (int t = 0; t < 2; t++) {
        int idx = tid + t * 256;
        int kr = idx >> 4, nn = (idx & 15) * 4;
        pv[t] = *(const float4*)(Bm + (size_t)kr * DEPTH_ + nn);
    }
#pragma unroll
    for (int t = 0; t < 4; t++) {
        int idx = tid + t * 256;
        int r = idx >> 3, c0 = (idx & 7) * 4;
        float* d = &As[(0 * 128 + r) * 40];
        d[perm8(c0 + 0)] = f2tf(pa[t].x); d[perm8(c0 + 1)] = f2tf(pa[t].y);
        d[perm8(c0 + 2)] = f2tf(pa[t].z); d[perm8(c0 + 3)] = f2tf(pa[t].w);
    }
#pragma unroll
    for (int t = 0; t < 2; t++) {
        int idx = tid + t * 256;
        int kr = idx >> 4, nn = (idx & 15) * 4;
        int pk = perm8(kr);
        Bs[(0 * 64 + nn + 0) * 40 + pk] = f2tf(pv[t].x);
        Bs[(0 * 64 + nn + 1) * 40 + pk] = f2tf(pv[t].y);
        Bs[(0 * 64 + nn + 2) * 40 + pk] = f2tf(pv[t].z);
        Bs[(0 * 64 + nn + 3) * 40 + pk] = f2tf(pv[t].w);
    }
    __syncthreads();

    const int nc = S_ / 32;   // 64
    for (int c = 0; c < nc; c++) {
        const int cur = c & 1;
        if (c + 1 < nc) {
            const int k0 = (c + 1) * 32;
#pragma unroll
            for (int t = 0; t < 4; t++) {
                int idx = tid + t * 256;
                int r = idx >> 3, c0 = (idx & 7) * 4;
                pa[t] = *(const float4*)(A + (size_t)(row0 + r) * S_ + k0 + c0);
            }
#pragma unroll
            for (int t = 0; t < 2; t++) {
                int idx = tid + t * 256;
                int kr = idx >> 4, nn = (idx & 15) * 4;
                pv[t] = *(const float4*)(Bm + (size_t)(k0 + kr) * DEPTH_ + nn);
            }
        }
#pragma unroll
        for (int ks = 0; ks < 4; ks++) {
            unsigned af[2][4], bf[4][2];
            const int kp = ks * 8 + (lane & 3) * 2;
#pragma unroll
            for (int mi = 0; mi < 2; mi++) {
                int r = wm * 32 + mi * 16 + (lane >> 2);
                float2 lo = *(const float2*)&As[(cur * 128 + r) * 40 + kp];
                float2 hi = *(const float2*)&As[(cur * 128 + r + 8) * 40 + kp];
                af[mi][0] = U(lo.x); af[mi][1] = U(hi.x);
                af[mi][2] = U(lo.y); af[mi][3] = U(hi.y);
            }
#pragma unroll
            for (int ni = 0; ni < 4; ni++) {
                int r = wn * 32 + ni * 8 + (lane >> 2);
                float2 bb = *(const float2*)&Bs[(cur * 64 + r) * 40 + kp];
                bf[ni][0] = U(bb.x); bf[ni][1] = U(bb.y);
            }
#pragma unroll
            for (int mi = 0; mi < 2; mi++)
#pragma unroll
                for (int ni = 0; ni < 4; ni++)
                    mma_tf32(acc[mi][ni][0], acc[mi][ni][1], acc[mi][ni][2], acc[mi][ni][3],
                             af[mi][0], af[mi][1], af[mi][2], af[mi][3],
                             bf[ni][0], bf[ni][1]);
        }
        if (c + 1 < nc) {
            const int nxt = 1 - cur;
#pragma unroll
            for (int t = 0; t < 4; t++) {
                int idx = tid + t * 256;
                int r = idx >> 3, c0 = (idx & 7) * 4;
                float* d = &As[(nxt * 128 + r) * 40];
                d[perm8(c0 + 0)] = f2tf(pa[t].x); d[perm8(c0 + 1)] = f2tf(pa[t].y);
                d[perm8(c0 + 2)] = f2tf(pa[t].z); d[perm8(c0 + 3)] = f2tf(pa[t].w);
            }
#pragma unroll
            for (int t = 0; t < 2; t++) {
                int idx = tid + t * 256;
                int kr = idx >> 4, nn = (idx & 15) * 4;
                int pk = perm8(kr);
                Bs[(nxt * 64 + nn + 0) * 40 + pk] = f2tf(pv[t].x);
                Bs[(nxt * 64 + nn + 1) * 40 + pk] = f2tf(pv[t].y);
                Bs[(nxt * 64 + nn + 2) * 40 + pk] = f2tf(pv[t].z);
                Bs[(nxt * 64 + nn + 3) * 40 + pk] = f2tf(pv[t].w);
            }
        }
        __syncthreads();
    }

    // Stage 128x64 tile (stride 72) then coalesced flush
    float* Cs = sm;   // 128*72 = 9216 floats, fits
#pragma unroll
    for (int mi = 0; mi < 2; mi++) {
#pragma unroll
        for (int ni = 0; ni < 4; ni++) {
            int r = wm * 32 + mi * 16 + (lane >> 2);
            int cc = wn * 32 + ni * 8 + (lane & 3) * 2;
            *(float2*)&Cs[r * 72 + cc] = make_float2(acc[mi][ni][0], acc[mi][ni][1]);
            *(float2*)&Cs[(r + 8) * 72 + cc] = make_float2(acc[mi][ni][2], acc[mi][ni][3]);
        }
    }
    __syncthreads();
#pragma unroll
    for (int t = 0; t < 8; t++) {
        int idx = tid + t * 256;
        int r = idx >> 4, c4 = (idx & 15) * 4;
        float4 val = *(const float4*)&Cs[r * 72 + c4];
        *(float4*)(ctx + ((size_t)(b * S_ + row0 + r)) * D_ + h * DEPTH_ + c4) = val;
    }
}

// ---------------------------------------------------------------------------
extern "C" void kernel_launch(void* const* d_in, const int* in_sizes, int n_in,
                              void* d_out, int out_size)
{
    const float* q    = (const float*)d_in[0];
    const float* k    = (const float*)d_in[1];
    const float* v    = (const float*)d_in[2];
    const float* mask = (const float*)d_in[3];
    const float* wq   = (const float*)d_in[4];
    const float* bq   = (const float*)d_in[5];
    const float* wk   = (const float*)d_in[6];
    const float* bk   = (const float*)d_in[7];
    const float* wv   = (const float*)d_in[8];
    const float* bv   = (const float*)d_in[9];
    const float* wo   = (const float*)d_in[10];
    const float* bo   = (const float*)d_in[11];

    float* out = (float*)d_out;

    float* attn;
    if ((size_t)out_size >= (size_t)OUT_ELEMS + ATTN_ELEMS) {
        attn = out + OUT_ELEMS;
    } else {
        cudaGetSymbolAddress((void**)&attn, g_attn_scratch);
    }

    float *Qh, *Kh, *Vh, *ctx;
    cudaGetSymbolAddress((void**)&Qh, g_Qh);
    cudaGetSymbolAddress((void**)&Kh, g_Kh);
    cudaGetSymbolAddress((void**)&Vh, g_Vh);
    cudaGetSymbolAddress((void**)&ctx, g_ctx);

    const int logitsSmem = 2 * 128 * 72 * sizeof(float);               // 73728
    const int ctxSmem = (2 * 128 * 40 + 2 * 64 * 40) * sizeof(float);  // 61440
    cudaFuncSetAttribute(logits_kernel, cudaFuncAttributeMaxDynamicSharedMemorySize, logitsSmem);
    cudaFuncSetAttribute(ctx_kernel, cudaFuncAttributeMaxDynamicSharedMemorySize, ctxSmem);

    dim3 qkvGrid(D_ / 128, M_ / 128, 3);          // (8, 32, 3)
    qkv_kernel<<<qkvGrid, 256>>>(q, k, v, wq, wk, wv, bq, bk, bv, Qh, Kh, Vh);

    dim3 logitsGrid(S_ / 128, S_ / 128, BH_);     // (16, 16, 32)
    logits_kernel<<<logitsGrid, 256, logitsSmem>>>(Qh, Kh, mask, attn);

    softmax_kernel<<<BH_ * S_, 256>>>(attn);      // 65536 rows

    dim3 ctxGrid(S_ / 128, BH_);                  // (16, 32)
    ctx_kernel<<<ctxGrid, 256, ctxSmem>>>(attn, Vh, ctx);

    dim3 projGrid(D_ / 128, M_ / 128);            // (8, 32)
    out_proj_kernel<<<projGrid, 256>>>(ctx, wo, bo, out);
}

// round 7
// speedup vs baseline: 1.3983x; 1.3983x over previous
#include <cuda_runtime.h>
#include <math.h>

// Problem constants
#define B_ 2
#define S_ 2048
#define D_ 1024
#define H_ 16
#define DEPTH_ 64
#define M_ (B_ * S_)            // 4096
#define BH_ (B_ * H_)           // 32
#define NT_ 16                  // 128-col tiles per attn row
#define OUT_ELEMS (B_ * S_ * D_)
#define ATTN_ELEMS ((size_t)BH_ * S_ * S_)

// Scratch
__device__ float g_Qh[(size_t)BH_ * S_ * DEPTH_];
__device__ float g_Kh[(size_t)BH_ * S_ * DEPTH_];
__device__ float g_Vh[(size_t)BH_ * S_ * DEPTH_];
__device__ float g_ctx[(size_t)M_ * D_];
__device__ float g_attn_scratch[ATTN_ELEMS];
// Softmax fusion stats
__device__ float g_tm[(size_t)BH_ * S_ * NT_];   // per-tile max
__device__ float g_ts[(size_t)BH_ * S_ * NT_];   // per-tile sum-exp (rel. tile max)
__device__ float g_rowM[BH_ * S_];               // row max
__device__ float g_rowInv[BH_ * S_];             // 1/denom

// ---------------------------------------------------------------------------
// tf32 helpers
// ---------------------------------------------------------------------------
__device__ __forceinline__ float f2tf(float x) {
    unsigned r; asm("cvt.rna.tf32.f32 %0, %1;" : "=r"(r) : "f"(x));
    return __uint_as_float(r);
}
__device__ __forceinline__ void mma_tf32(
    float& c0, float& c1, float& c2, float& c3,
    unsigned a0, unsigned a1, unsigned a2, unsigned a3,
    unsigned b0, unsigned b1)
{
    asm volatile(
        "mma.sync.aligned.m16n8k8.row.col.f32.tf32.tf32.f32 "
        "{%0,%1,%2,%3}, {%4,%5,%6,%7}, {%8,%9}, {%0,%1,%2,%3};"
        : "+f"(c0), "+f"(c1), "+f"(c2), "+f"(c3)
        : "r"(a0), "r"(a1), "r"(a2), "r"(a3), "r"(b0), "r"(b1));
}
#define U(x) __float_as_uint(x)

// ---------------------------------------------------------------------------
// Projection GEMM body (R5-proven): P = X @ W + b.
// CTA 128x128, BK=16 double-buffered, 8 warps (2m x 4n), warp 64x32.
// ---------------------------------------------------------------------------
__device__ __forceinline__ void proj_body(
    const float* __restrict__ X, const float* __restrict__ W,
    const float* __restrict__ bias, float* __restrict__ out, int headsplit)
{
    __shared__ float As[2][128][20];
    __shared__ float Bs[2][128][20];
    const int tid = threadIdx.x, lane = tid & 31, wid = tid >> 5;
    const int wm = wid & 1, wn = wid >> 1;
    const int row0 = blockIdx.y * 128, col0 = blockIdx.x * 128;

    const int far = tid >> 2, fac = (tid & 3) * 4;
    const int fwk = tid >> 5, fwn = (tid & 31) * 4;

    float acc[4][4][4];
#pragma unroll
    for (int mi = 0; mi < 4; mi++)
#pragma unroll
        for (int ni = 0; ni < 4; ni++)
#pragma unroll
            for (int t = 0; t < 4; t++) acc[mi][ni][t] = 0.f;

    float4 pa0, pa1, pw0, pw1;
    pa0 = *(const float4*)(X + (size_t)(row0 + far) * D_ + fac);
    pa1 = *(const float4*)(X + (size_t)(row0 + far + 64) * D_ + fac);
    pw0 = *(const float4*)(W + (size_t)fwk * D_ + col0 + fwn);
    pw1 = *(const float4*)(W + (size_t)(fwk + 8) * D_ + col0 + fwn);
    {
        float* a = &As[0][far][fac];
        a[0] = f2tf(pa0.x); a[1] = f2tf(pa0.y); a[2] = f2tf(pa0.z); a[3] = f2tf(pa0.w);
        float* a2 = &As[0][far + 64][fac];
        a2[0] = f2tf(pa1.x); a2[1] = f2tf(pa1.y); a2[2] = f2tf(pa1.z); a2[3] = f2tf(pa1.w);
        Bs[0][fwn + 0][fwk] = f2tf(pw0.x); Bs[0][fwn + 1][fwk] = f2tf(pw0.y);
        Bs[0][fwn + 2][fwk] = f2tf(pw0.z); Bs[0][fwn + 3][fwk] = f2tf(pw0.w);
        Bs[0][fwn + 0][fwk + 8] = f2tf(pw1.x); Bs[0][fwn + 1][fwk + 8] = f2tf(pw1.y);
        Bs[0][fwn + 2][fwk + 8] = f2tf(pw1.z); Bs[0][fwn + 3][fwk + 8] = f2tf(pw1.w);
    }
    __syncthreads();

    const int nc = D_ / 16;
    for (int c = 0; c < nc; c++) {
        const int cur = c & 1;
        if (c + 1 < nc) {
            const int k0 = (c + 1) * 16;
            pa0 = *(const float4*)(X + (size_t)(row0 + far) * D_ + k0 + fac);
            pa1 = *(const float4*)(X + (size_t)(row0 + far + 64) * D_ + k0 + fac);
            pw0 = *(const float4*)(W + (size_t)(k0 + fwk) * D_ + col0 + fwn);
            pw1 = *(const float4*)(W + (size_t)(k0 + fwk + 8) * D_ + col0 + fwn);
        }
#pragma unroll
        for (int ks = 0; ks < 2; ks++) {
            unsigned af[4][4], bf[4][2];
#pragma unroll
            for (int mi = 0; mi < 4; mi++) {
                const float* p = &As[cur][wm * 64 + mi * 16 + (lane >> 2)][ks * 8 + (lane & 3)];
                af[mi][0] = U(p[0]); af[mi][1] = U(p[8 * 20]);
                af[mi][2] = U(p[4]); af[mi][3] = U(p[8 * 20 + 4]);
            }
#pragma unroll
            for (int ni = 0; ni < 4; ni++) {
                const float* p = &Bs[cur][wn * 32 + ni * 8 + (lane >> 2)][ks * 8 + (lane & 3)];
                bf[ni][0] = U(p[0]); bf[ni][1] = U(p[4]);
            }
#pragma unroll
            for (int mi = 0; mi < 4; mi++)
#pragma unroll
                for (int ni = 0; ni < 4; ni++)
                    mma_tf32(acc[mi][ni][0], acc[mi][ni][1], acc[mi][ni][2], acc[mi][ni][3],
                             af[mi][0], af[mi][1], af[mi][2], af[mi][3],
                             bf[ni][0], bf[ni][1]);
        }
        if (c + 1 < nc) {
            const int nxt = 1 - cur;
            float* a = &As[nxt][far][fac];
            a[0] = f2tf(pa0.x); a[1] = f2tf(pa0.y); a[2] = f2tf(pa0.z); a[3] = f2tf(pa0.w);
            float* a2 = &As[nxt][far + 64][fac];
            a2[0] = f2tf(pa1.x); a2[1] = f2tf(pa1.y); a2[2] = f2tf(pa1.z); a2[3] = f2tf(pa1.w);
            Bs[nxt][fwn + 0][fwk] = f2tf(pw0.x); Bs[nxt][fwn + 1][fwk] = f2tf(pw0.y);
            Bs[nxt][fwn + 2][fwk] = f2tf(pw0.z); Bs[nxt][fwn + 3][fwk] = f2tf(pw0.w);
            Bs[nxt][fwn + 0][fwk + 8] = f2tf(pw1.x); Bs[nxt][fwn + 1][fwk + 8] = f2tf(pw1.y);
            Bs[nxt][fwn + 2][fwk + 8] = f2tf(pw1.z); Bs[nxt][fwn + 3][fwk + 8] = f2tf(pw1.w);
        }
        __syncthreads();
    }

#pragma unroll
    for (int mi = 0; mi < 4; mi++) {
#pragma unroll
        for (int ni = 0; ni < 4; ni++) {
            int r = row0 + wm * 64 + mi * 16 + (lane >> 2);
            int cc = col0 + wn * 32 + ni * 8 + (lane & 3) * 2;
            float2 bb = *(const float2*)(bias + cc);
            float2 v0 = make_float2(acc[mi][ni][0] + bb.x, acc[mi][ni][1] + bb.y);
            float2 v1 = make_float2(acc[mi][ni][2] + bb.x, acc[mi][ni][3] + bb.y);
            if (headsplit) {
                int b = r >> 11, s = r & 2047;
                int h = cc >> 6, d = cc & 63;
                float* dst = out + ((size_t)(b * H_ + h) * S_ + s) * DEPTH_ + d;
                *(float2*)dst = v0;
                *(float2*)(dst + 8 * DEPTH_) = v1;
            } else {
                float* dst = out + (size_t)r * D_ + cc;
                *(float2*)dst = v0;
                *(float2*)(dst + 8 * D_) = v1;
            }
        }
    }
}

// Merged Q/K/V projection (grid.z selects projection)
__global__ __launch_bounds__(256, 2) void qkv_kernel(
    const float* __restrict__ q, const float* __restrict__ k, const float* __restrict__ v,
    const float* __restrict__ wq, const float* __restrict__ wk, const float* __restrict__ wv,
    const float* __restrict__ bq, const float* __restrict__ bk, const float* __restrict__ bv,
    float* __restrict__ Qh, float* __restrict__ Kh, float* __restrict__ Vh)
{
    const int z = blockIdx.z;
    const float* X = (z == 0) ? q : (z == 1) ? k : v;
    const float* W = (z == 0) ? wq : (z == 1) ? wk : wv;
    const float* bias = (z == 0) ? bq : (z == 1) ? bk : bv;
    float* out = (z == 0) ? Qh : (z == 1) ? Kh : Vh;
    proj_body(X, W, bias, out, 1);
}

__global__ __launch_bounds__(256, 2) void out_proj_kernel(
    const float* __restrict__ X, const float* __restrict__ W,
    const float* __restrict__ bias, float* __restrict__ out)
{
    proj_body(X, W, bias, out, 0);
}

// ---------------------------------------------------------------------------
// Logits (R5 base): C = Qh @ Kh^T * 0.125 + mask*1e-9 (raw, pre-softmax)
// PLUS per-(row, tile) max / sum-exp stats for fused softmax.
// Dynamic smem: 2*128*68 floats.
// ---------------------------------------------------------------------------
__global__ __launch_bounds__(256, 2) void logits_kernel(
    const float* __restrict__ Qh, const float* __restrict__ Kh,
    const float* __restrict__ mask, float* __restrict__ attn,
    float* __restrict__ tm, float* __restrict__ ts)
{
    extern __shared__ float sm[];
    float (*As)[68] = (float(*)[68])sm;
    float (*Bs)[68] = (float(*)[68])(sm + 128 * 68);

    const int bh = blockIdx.z;
    const float* A = Qh + (size_t)bh * S_ * DEPTH_;
    const float* Bm = Kh + (size_t)bh * S_ * DEPTH_;
    float* C = attn + (size_t)bh * S_ * S_;
    const int bidx = bh >> 4;

    const int tid = threadIdx.x, lane = tid & 31, wid = tid >> 5;
    const int wm = wid & 1, wn = wid >> 1;
    const int row0 = blockIdx.y * 128, col0 = blockIdx.x * 128;

#pragma unroll
    for (int t = 0; t < 8; t++) {
        int idx = tid + t * 256;
        int r = idx >> 4, cc = (idx & 15) * 4;
        float4 x = *(const float4*)(A + (size_t)(row0 + r) * DEPTH_ + cc);
        float* d = &As[r][cc];
        d[0] = f2tf(x.x); d[1] = f2tf(x.y); d[2] = f2tf(x.z); d[3] = f2tf(x.w);
        float4 y = *(const float4*)(Bm + (size_t)(col0 + r) * DEPTH_ + cc);
        float* e = &Bs[r][cc];
        e[0] = f2tf(y.x); e[1] = f2tf(y.y); e[2] = f2tf(y.z); e[3] = f2tf(y.w);
    }
    __syncthreads();

    float acc[4][4][4];
#pragma unroll
    for (int mi = 0; mi < 4; mi++)
#pragma unroll
        for (int ni = 0; ni < 4; ni++)
#pragma unroll
            for (int t = 0; t < 4; t++) acc[mi][ni][t] = 0.f;

#pragma unroll
    for (int ks = 0; ks < 8; ks++) {
        unsigned af[4][4], bf[4][2];
#pragma unroll
        for (int mi = 0; mi < 4; mi++) {
            const float* p = &As[wm * 64 + mi * 16 + (lane >> 2)][ks * 8 + (lane & 3)];
            af[mi][0] = U(p[0]); af[mi][1] = U(p[8 * 68]);
            af[mi][2] = U(p[4]); af[mi][3] = U(p[8 * 68 + 4]);
        }
#pragma unroll
        for (int ni = 0; ni < 4; ni++) {
            const float* p = &Bs[wn * 32 + ni * 8 + (lane >> 2)][ks * 8 + (lane & 3)];
            bf[ni][0] = U(p[0]); bf[ni][1] = U(p[4]);
        }
#pragma unroll
        for (int mi = 0; mi < 4; mi++)
#pragma unroll
            for (int ni = 0; ni < 4; ni++)
                mma_tf32(acc[mi][ni][0], acc[mi][ni][1], acc[mi][ni][2], acc[mi][ni][3],
                         af[mi][0], af[mi][1], af[mi][2], af[mi][3],
                         bf[ni][0], bf[ni][1]);
    }

    // Epilogue: v = acc*0.125 + mask*1e-9 (into acc), write raw to C.
#pragma unroll
    for (int mi = 0; mi < 4; mi++) {
#pragma unroll
        for (int ni = 0; ni < 4; ni++) {
            int q = row0 + wm * 64 + mi * 16 + (lane >> 2);
            int kc = col0 + wn * 32 + ni * 8 + (lane & 3) * 2;
            const float* mrow = mask + ((size_t)bidx * S_ + q) * S_ + kc;
            float2 m0 = *(const float2*)mrow;
            float2 m1 = *(const float2*)(mrow + 8 * S_);
            acc[mi][ni][0] = acc[mi][ni][0] * 0.125f + m0.x * 1e-9f;
            acc[mi][ni][1] = acc[mi][ni][1] * 0.125f + m0.y * 1e-9f;
            acc[mi][ni][2] = acc[mi][ni][2] * 0.125f + m1.x * 1e-9f;
            acc[mi][ni][3] = acc[mi][ni][3] * 0.125f + m1.y * 1e-9f;
            float* dst = C + (size_t)q * S_ + kc;
            *(float2*)dst = make_float2(acc[mi][ni][0], acc[mi][ni][1]);
            *(float2*)(dst + 8 * S_) = make_float2(acc[mi][ni][2], acc[mi][ni][3]);
        }
    }

    // ---- Tile softmax stats: per-row max and sum-exp over this 128-col tile
    __syncthreads();                       // As/Bs dead; reuse smem
    float* pm = sm;                        // [128][4]
    float* Ms = sm + 512;                  // [128]
    float* ps = sm + 768;                  // [128][4]

#pragma unroll
    for (int mi = 0; mi < 4; mi++) {
#pragma unroll
        for (int h = 0; h < 2; h++) {
            float m = -1e30f;
#pragma unroll
            for (int ni = 0; ni < 4; ni++)
                m = fmaxf(m, fmaxf(acc[mi][ni][2 * h], acc[mi][ni][2 * h + 1]));
            m = fmaxf(m, __shfl_xor_sync(~0u, m, 1));
            m = fmaxf(m, __shfl_xor_sync(~0u, m, 2));
            if ((lane & 3) == 0)
                pm[(wm * 64 + mi * 16 + (lane >> 2) + h * 8) * 4 + wn] = m;
        }
    }
    __syncthreads();
    if (tid < 128)
        Ms[tid] = fmaxf(fmaxf(pm[tid * 4], pm[tid * 4 + 1]),
                        fmaxf(pm[tid * 4 + 2], pm[tid * 4 + 3]));
    __syncthreads();
#pragma unroll
    for (int mi = 0; mi < 4; mi++) {
#pragma unroll
        for (int h = 0; h < 2; h++) {
            int rloc = wm * 64 + mi * 16 + (lane >> 2) + h * 8;
            float M = Ms[rloc];
            float s = 0.f;
#pragma unroll
            for (int ni = 0; ni < 4; ni++)
                s += __expf(acc[mi][ni][2 * h] - M) + __expf(acc[mi][ni][2 * h + 1] - M);
            s += __shfl_xor_sync(~0u, s, 1);
            s += __shfl_xor_sync(~0u, s, 2);
            if ((lane & 3) == 0) ps[rloc * 4 + wn] = s;
        }
    }
    __syncthreads();
    if (tid < 128) {
        float s = ps[tid * 4] + ps[tid * 4 + 1] + ps[tid * 4 + 2] + ps[tid * 4 + 3];
        size_t idx = ((size_t)bh * S_ + row0 + tid) * NT_ + blockIdx.x;
        tm[idx] = Ms[tid];
        ts[idx] = s;
    }
}

// ---------------------------------------------------------------------------
// Row stats: combine 16 tile stats -> (rowMax, 1/denom). 65536 rows.
// ---------------------------------------------------------------------------
__global__ __launch_bounds__(256) void rowstats_kernel(
    const float* __restrict__ tm, const float* __restrict__ ts,
    float* __restrict__ rowM, float* __restrict__ rowInv)
{
    int row = blockIdx.x * 256 + threadIdx.x;
    const float4* m4 = (const float4*)(tm + (size_t)row * NT_);
    const float4* s4 = (const float4*)(ts + (size_t)row * NT_);
    float4 ma = m4[0], mb = m4[1], mc = m4[2], md = m4[3];
    float M = fmaxf(fmaxf(fmaxf(ma.x, ma.y), fmaxf(ma.z, ma.w)),
                    fmaxf(fmaxf(fmaxf(mb.x, mb.y), fmaxf(mb.z, mb.w)),
                          fmaxf(fmaxf(fmaxf(mc.x, mc.y), fmaxf(mc.z, mc.w)),
                                fmaxf(fmaxf(md.x, md.y), fmaxf(md.z, md.w)))));
    float4 sa = s4[0], sb = s4[1], sc = s4[2], sd = s4[3];
    float d = sa.x * __expf(ma.x - M) + sa.y * __expf(ma.y - M)
            + sa.z * __expf(ma.z - M) + sa.w * __expf(ma.w - M)
            + sb.x * __expf(mb.x - M) + sb.y * __expf(mb.y - M)
            + sb.z * __expf(mb.z - M) + sb.w * __expf(mb.w - M)
            + sc.x * __expf(mc.x - M) + sc.y * __expf(mc.y - M)
            + sc.z * __expf(mc.z - M) + sc.w * __expf(mc.w - M)
            + sd.x * __expf(md.x - M) + sd.y * __expf(md.y - M)
            + sd.z * __expf(md.z - M) + sd.w * __expf(md.w - M);
    rowM[row] = M;
    rowInv[row] = 1.f / d;
}

// ---------------------------------------------------------------------------
// ctx = softmax(attn_raw) @ Vh; also writes normalized probs back to attn.
// R5 base: CTA 128m x 64n, BK=32 double-buffered, 8 warps (4m x 2n).
// Dynamic smem: 2*128*36 + 2*64*36 floats.
// ---------------------------------------------------------------------------
__global__ __launch_bounds__(256, 2) void ctx_kernel(
    float* __restrict__ attn, const float* __restrict__ Vh,
    const float* __restrict__ rowMg, const float* __restrict__ rowInvg,
    float* __restrict__ ctx)
{
    extern __shared__ float sm[];
    float (*As)[128][36] = (float(*)[128][36])sm;
    float (*Bs)[64][36]  = (float(*)[64][36])(sm + 2 * 128 * 36);
    __shared__ float rowM[128], rowInv[128];

    const int bh = blockIdx.y;
    float* A = attn + (size_t)bh * S_ * S_;
    const float* Bm = Vh + (size_t)bh * S_ * DEPTH_;
    const int b = bh >> 4, h = bh & 15;

    const int tid = threadIdx.x, lane = tid & 31, wid = tid >> 5;
    const int wm = wid & 3, wn = wid >> 2;
    const int row0 = blockIdx.x * 128;

    if (tid < 128) {
        rowM[tid] = rowMg[bh * S_ + row0 + tid];
        rowInv[tid] = rowInvg[bh * S_ + row0 + tid];
    }

    float acc[2][4][4];
#pragma unroll
    for (int mi = 0; mi < 2; mi++)
#pragma unroll
        for (int ni = 0; ni < 4; ni++)
#pragma unroll
            for (int t = 0; t < 4; t++) acc[mi][ni][t] = 0.f;

    float4 pa[4], pv[2];
#pragma unroll
    for (int t = 0; t < 4; t++) {
        int idx = tid + t * 256;
        int r = idx >> 3, c0 = (idx & 7) * 4;
        pa[t] = *(const float4*)(A + (size_t)(row0 + r) * S_ + c0);
    }
#pragma unroll
    for (int t = 0; t < 2; t++) {
        int idx = tid + t * 256;
        int kr = idx >> 4, nn = (idx & 15) * 4;
        pv[t] = *(const float4*)(Bm + (size_t)kr * DEPTH_ + nn);
    }
    __syncthreads();   // rowM/rowInv ready

#pragma unroll
    for (int t = 0; t < 4; t++) {
        int idx = tid + t * 256;
        int r = idx >> 3, c0 = (idx & 7) * 4;
        float M = rowM[r], inv = rowInv[r];
        float4 p = make_float4(__expf(pa[t].x - M) * inv, __expf(pa[t].y - M) * inv,
                               __expf(pa[t].z - M) * inv, __expf(pa[t].w - M) * inv);
        *(float4*)(A + (size_t)(row0 + r) * S_ + c0) = p;   // normalized attn out
        float* d = &As[0][r][c0];
        d[0] = f2tf(p.x); d[1] = f2tf(p.y); d[2] = f2tf(p.z); d[3] = f2tf(p.w);
    }
#pragma unroll
    for (int t = 0; t < 2; t++) {
        int idx = tid + t * 256;
        int kr = idx >> 4, nn = (idx & 15) * 4;
        Bs[0][nn + 0][kr] = f2tf(pv[t].x);
        Bs[0][nn + 1][kr] = f2tf(pv[t].y);
        Bs[0][nn + 2][kr] = f2tf(pv[t].z);
        Bs[0][nn + 3][kr] = f2tf(pv[t].w);
    }
    __syncthreads();

    const int nc = S_ / 32;   // 64
    for (int c = 0; c < nc; c++) {
        const int cur = c & 1;
        const int k0n = (c + 1) * 32;
        if (c + 1 < nc) {
#pragma unroll
            for (int t = 0; t < 4; t++) {
                int idx = tid + t * 256;
                int r = idx >> 3, c0 = (idx & 7) * 4;
                pa[t] = *(const float4*)(A + (size_t)(row0 + r) * S_ + k0n + c0);
            }
#pragma unroll
            for (int t = 0; t < 2; t++) {
                int idx = tid + t * 256;
                int kr = idx >> 4, nn = (idx & 15) * 4;
                pv[t] = *(const float4*)(Bm + (size_t)(k0n + kr) * DEPTH_ + nn);
            }
        }
#pragma unroll
        for (int ks = 0; ks < 4; ks++) {
            unsigned af[2][4], bf[4][2];
#pragma unroll
            for (int mi = 0; mi < 2; mi++) {
                const float* p = &As[cur][wm * 32 + mi * 16 + (lane >> 2)][ks * 8 + (lane & 3)];
                af[mi][0] = U(p[0]); af[mi][1] = U(p[8 * 36]);
                af[mi][2] = U(p[4]); af[mi][3] = U(p[8 * 36 + 4]);
            }
#pragma unroll
            for (int ni = 0; ni < 4; ni++) {
                const float* p = &Bs[cur][wn * 32 + ni * 8 + (lane >> 2)][ks * 8 + (lane & 3)];
                bf[ni][0] = U(p[0]); bf[ni][1] = U(p[4]);
            }
#pragma unroll
            for (int mi = 0; mi < 2; mi++)
#pragma unroll
                for (int ni = 0; ni < 4; ni++)
                    mma_tf32(acc[mi][ni][0], acc[mi][ni][1], acc[mi][ni][2], acc[mi][ni][3],
                             af[mi][0], af[mi][1], af[mi][2], af[mi][3],
                             bf[ni][0], bf[ni][1]);
        }
        if (c + 1 < nc) {
            const int nxt = 1 - cur;
#pragma unroll
            for (int t = 0; t < 4; t++) {
                int idx = tid + t * 256;
                int r = idx >> 3, c0 = (idx & 7) * 4;
                float M = rowM[r], inv = rowInv[r];
                float4 p = make_float4(__expf(pa[t].x - M) * inv, __expf(pa[t].y - M) * inv,
                                       __expf(pa[t].z - M) * inv, __expf(pa[t].w - M) * inv);
                *(float4*)(A + (size_t)(row0 + r) * S_ + k0n + c0) = p;
                float* d = &As[nxt][r][c0];
                d[0] = f2tf(p.x); d[1] = f2tf(p.y); d[2] = f2tf(p.z); d[3] = f2tf(p.w);
            }
#pragma unroll
            for (int t = 0; t < 2; t++) {
                int idx = tid + t * 256;
                int kr = idx >> 4, nn = (idx & 15) * 4;
                Bs[nxt][nn + 0][kr] = f2tf(pv[t].x);
                Bs[nxt][nn + 1][kr] = f2tf(pv[t].y);
                Bs[nxt][nn + 2][kr] = f2tf(pv[t].z);
                Bs[nxt][nn + 3][kr] = f2tf(pv[t].w);
            }
        }
        __syncthreads();
    }

#pragma unroll
    for (int mi = 0; mi < 2; mi++) {
#pragma unroll
        for (int ni = 0; ni < 4; ni++) {
            int s = row0 + wm * 32 + mi * 16 + (lane >> 2);
            int cc = wn * 32 + ni * 8 + (lane & 3) * 2;
            float* dst = ctx + ((size_t)(b * S_ + s)) * D_ + h * DEPTH_ + cc;
            *(float2*)dst = make_float2(acc[mi][ni][0], acc[mi][ni][1]);
            *(float2*)(dst + 8 * D_) = make_float2(acc[mi][ni][2], acc[mi][ni][3]);
        }
    }
}

// ---------------------------------------------------------------------------
extern "C" void kernel_launch(void* const* d_in, const int* in_sizes, int n_in,
                              void* d_out, int out_size)
{
    const float* q    = (const float*)d_in[0];
    const float* k    = (const float*)d_in[1];
    const float* v    = (const float*)d_in[2];
    const float* mask = (const float*)d_in[3];
    const float* wq   = (const float*)d_in[4];
    const float* bq   = (const float*)d_in[5];
    const float* wk   = (const float*)d_in[6];
    const float* bk   = (const float*)d_in[7];
    const float* wv   = (const float*)d_in[8];
    const float* bv   = (const float*)d_in[9];
    const float* wo   = (const float*)d_in[10];
    const float* bo   = (const float*)d_in[11];

    float* out = (float*)d_out;

    float* attn;
    if ((size_t)out_size >= (size_t)OUT_ELEMS + ATTN_ELEMS) {
        attn = out + OUT_ELEMS;
    } else {
        cudaGetSymbolAddress((void**)&attn, g_attn_scratch);
    }

    float *Qh, *Kh, *Vh, *ctx, *tm, *ts, *rowM, *rowInv;
    cudaGetSymbolAddress((void**)&Qh, g_Qh);
    cudaGetSymbolAddress((void**)&Kh, g_Kh);
    cudaGetSymbolAddress((void**)&Vh, g_Vh);
    cudaGetSymbolAddress((void**)&ctx, g_ctx);
    cudaGetSymbolAddress((void**)&tm, g_tm);
    cudaGetSymbolAddress((void**)&ts, g_ts);
    cudaGetSymbolAddress((void**)&rowM, g_rowM);
    cudaGetSymbolAddress((void**)&rowInv, g_rowInv);

    const int logitsSmem = 2 * 128 * 68 * sizeof(float);
    const int ctxSmem = (2 * 128 * 36 + 2 * 64 * 36) * sizeof(float);
    cudaFuncSetAttribute(logits_kernel, cudaFuncAttributeMaxDynamicSharedMemorySize, logitsSmem);
    cudaFuncSetAttribute(ctx_kernel, cudaFuncAttributeMaxDynamicSharedMemorySize, ctxSmem);

    dim3 qkvGrid(D_ / 128, M_ / 128, 3);
    qkv_kernel<<<qkvGrid, 256>>>(q, k, v, wq, wk, wv, bq, bk, bv, Qh, Kh, Vh);

    dim3 logitsGrid(S_ / 128, S_ / 128, BH_);
    logits_kernel<<<logitsGrid, 256, logitsSmem>>>(Qh, Kh, mask, attn, tm, ts);

    rowstats_kernel<<<(BH_ * S_) / 256, 256>>>(tm, ts, rowM, rowInv);

    dim3 ctxGrid(S_ / 128, BH_);
    ctx_kernel<<<ctxGrid, 256, ctxSmem>>>(attn, Vh, rowM, rowInv, ctx);

    dim3 projGrid(D_ / 128, M_ / 128);
    out_proj_kernel<<<projGrid, 256>>>(ctx, wo, bo, out);
}

// round 9
// speedup vs baseline: 1.8553x; 1.3268x over previous
#include <cuda_runtime.h>
#include <cuda_fp16.h>
#include <math.h>

// Problem constants
#define B_ 2
#define S_ 2048
#define D_ 1024
#define H_ 16
#define DEPTH_ 64
#define M_ (B_ * S_)            // 4096
#define BH_ (B_ * H_)           // 32
#define NT_ 16                  // 128-col tiles per attn row
#define OUT_ELEMS (B_ * S_ * D_)
#define ATTN_ELEMS ((size_t)BH_ * S_ * S_)

// Scratch
__device__ float g_Qh[(size_t)BH_ * S_ * DEPTH_];
__device__ float g_Kh[(size_t)BH_ * S_ * DEPTH_];
__device__ float g_Vh[(size_t)BH_ * S_ * DEPTH_];
__device__ float g_ctx[(size_t)M_ * D_];
__device__ float g_attn_scratch[ATTN_ELEMS];
// Softmax fusion stats
__device__ float g_tm[(size_t)BH_ * S_ * NT_];
__device__ float g_ts[(size_t)BH_ * S_ * NT_];
__device__ float g_rowM[BH_ * S_];
__device__ float g_rowInv[BH_ * S_];

// ---------------------------------------------------------------------------
// tf32 helpers (logits/ctx unchanged from R7)
// ---------------------------------------------------------------------------
__device__ __forceinline__ float f2tf(float x) {
    unsigned r; asm("cvt.rna.tf32.f32 %0, %1;" : "=r"(r) : "f"(x));
    return __uint_as_float(r);
}
__device__ __forceinline__ void mma_tf32(
    float& c0, float& c1, float& c2, float& c3,
    unsigned a0, unsigned a1, unsigned a2, unsigned a3,
    unsigned b0, unsigned b1)
{
    asm volatile(
        "mma.sync.aligned.m16n8k8.row.col.f32.tf32.tf32.f32 "
        "{%0,%1,%2,%3}, {%4,%5,%6,%7}, {%8,%9}, {%0,%1,%2,%3};"
        : "+f"(c0), "+f"(c1), "+f"(c2), "+f"(c3)
        : "r"(a0), "r"(a1), "r"(a2), "r"(a3), "r"(b0), "r"(b1));
}
#define U(x) __float_as_uint(x)

// ---------------------------------------------------------------------------
// fp16 helpers (projections)
// ---------------------------------------------------------------------------
__device__ __forceinline__ unsigned h2pack(float a, float b) {
    __half2 h = __floats2half2_rn(a, b);
    return *(unsigned*)&h;
}
__device__ __forceinline__ void ldsm4(unsigned* r, const __half* p) {
    unsigned a = (unsigned)__cvta_generic_to_shared(p);
    asm volatile("ldmatrix.sync.aligned.m8n8.x4.shared.b16 {%0,%1,%2,%3}, [%4];"
                 : "=r"(r[0]), "=r"(r[1]), "=r"(r[2]), "=r"(r[3]) : "r"(a));
}
__device__ __forceinline__ void ldsm4t(unsigned* r, const __half* p) {
    unsigned a = (unsigned)__cvta_generic_to_shared(p);
    asm volatile("ldmatrix.sync.aligned.m8n8.x4.trans.shared.b16 {%0,%1,%2,%3}, [%4];"
                 : "=r"(r[0]), "=r"(r[1]), "=r"(r[2]), "=r"(r[3]) : "r"(a));
}
__device__ __forceinline__ void mma_f16(float* c, const unsigned* a, const unsigned* b) {
    asm volatile(
        "mma.sync.aligned.m16n8k16.row.col.f32.f16.f16.f32 "
        "{%0,%1,%2,%3}, {%4,%5,%6,%7}, {%8,%9}, {%0,%1,%2,%3};"
        : "+f"(c[0]), "+f"(c[1]), "+f"(c[2]), "+f"(c[3])
        : "r"(a[0]), "r"(a[1]), "r"(a[2]), "r"(a[3]), "r"(b[0]), "r"(b[1]));
}

// ---------------------------------------------------------------------------
// Projection GEMM body, fp16 mma: P = X @ W + b. X:[4096,1024] W:[1024,1024]
// CTA 128x128, BK=32 double-buffered, 8 warps (2m x 4n), warp 64x32.
// As [m][k] halfs (stride 40), Bs [k][n] halfs (stride 136).
// ---------------------------------------------------------------------------
__device__ __forceinline__ void proj_body(
    const float* __restrict__ X, const float* __restrict__ W,
    const float* __restrict__ bias, float* __restrict__ out, int headsplit)
{
    __shared__ __align__(16) __half As[2][128][40];
    __shared__ __align__(16) __half Bs[2][32][136];
    const int tid = threadIdx.x, lane = tid & 31, wid = tid >> 5;
    const int wm = wid & 1, wn = wid >> 1;
    const int row0 = blockIdx.y * 128, col0 = blockIdx.x * 128;

    const int arow = tid >> 1, akoff = (tid & 1) * 16;   // A fill
    const int bkrow = tid >> 3, bnoff = (tid & 7) * 16;  // B fill

    float acc[4][4][4];
#pragma unroll
    for (int mi = 0; mi < 4; mi++)
#pragma unroll
        for (int ni = 0; ni < 4; ni++)
#pragma unroll
            for (int t = 0; t < 4; t++) acc[mi][ni][t] = 0.f;

    uint4 au0, au1, bu0, bu1;
    {
        const float* xp = X + (size_t)(row0 + arow) * D_ + akoff;
        float4 x0 = *(const float4*)xp, x1 = *(const float4*)(xp + 4);
        float4 x2 = *(const float4*)(xp + 8), x3 = *(const float4*)(xp + 12);
        au0 = make_uint4(h2pack(x0.x, x0.y), h2pack(x0.z, x0.w),
                         h2pack(x1.x, x1.y), h2pack(x1.z, x1.w));
        au1 = make_uint4(h2pack(x2.x, x2.y), h2pack(x2.z, x2.w),
                         h2pack(x3.x, x3.y), h2pack(x3.z, x3.w));
        const float* wp = W + (size_t)bkrow * D_ + col0 + bnoff;
        float4 w0 = *(const float4*)wp, w1 = *(const float4*)(wp + 4);
        float4 w2 = *(const float4*)(wp + 8), w3 = *(const float4*)(wp + 12);
        bu0 = make_uint4(h2pack(w0.x, w0.y), h2pack(w0.z, w0.w),
                         h2pack(w1.x, w1.y), h2pack(w1.z, w1.w));
        bu1 = make_uint4(h2pack(w2.x, w2.y), h2pack(w2.z, w2.w),
                         h2pack(w3.x, w3.y), h2pack(w3.z, w3.w));
        *(uint4*)&As[0][arow][akoff] = au0;
        *(uint4*)&As[0][arow][akoff + 8] = au1;
        *(uint4*)&Bs[0][bkrow][bnoff] = bu0;
        *(uint4*)&Bs[0][bkrow][bnoff + 8] = bu1;
    }
    __syncthreads();

    const int nc = D_ / 32;   // 32
    for (int c = 0; c < nc; c++) {
        const int cur = c & 1;
        if (c + 1 < nc) {
            const int k0 = (c + 1) * 32;
            const float* xp = X + (size_t)(row0 + arow) * D_ + k0 + akoff;
            float4 x0 = *(const float4*)xp, x1 = *(const float4*)(xp + 4);
            float4 x2 = *(const float4*)(xp + 8), x3 = *(const float4*)(xp + 12);
            au0 = make_uint4(h2pack(x0.x, x0.y), h2pack(x0.z, x0.w),
                             h2pack(x1.x, x1.y), h2pack(x1.z, x1.w));
            au1 = make_uint4(h2pack(x2.x, x2.y), h2pack(x2.z, x2.w),
                             h2pack(x3.x, x3.y), h2pack(x3.z, x3.w));
            const float* wp = W + (size_t)(k0 + bkrow) * D_ + col0 + bnoff;
            float4 w0 = *(const float4*)wp, w1 = *(const float4*)(wp + 4);
            float4 w2 = *(const float4*)(wp + 8), w3 = *(const float4*)(wp + 12);
            bu0 = make_uint4(h2pack(w0.x, w0.y), h2pack(w0.z, w0.w),
                             h2pack(w1.x, w1.y), h2pack(w1.z, w1.w));
            bu1 = make_uint4(h2pack(w2.x, w2.y), h2pack(w2.z, w2.w),
                             h2pack(w3.x, w3.y), h2pack(w3.z, w3.w));
        }
#pragma unroll
        for (int ks = 0; ks < 2; ks++) {
            const int k = ks * 16;
            unsigned af[4][4], bf[4][2];
#pragma unroll
            for (int mi = 0; mi < 4; mi++) {
                int r = wm * 64 + mi * 16 + (lane & 15);
                ldsm4(af[mi], &As[cur][r][k + ((lane >> 4) << 3)]);
            }
#pragma unroll
            for (int np = 0; np < 2; np++) {
                unsigned bb[4];
                int kr = k + (lane & 7) + ((lane >> 3) & 1) * 8;
                int nn = wn * 32 + np * 16 + (lane >> 4) * 8;
                ldsm4t(bb, &Bs[cur][kr][nn]);
                bf[np * 2 + 0][0] = bb[0]; bf[np * 2 + 0][1] = bb[1];
                bf[np * 2 + 1][0] = bb[2]; bf[np * 2 + 1][1] = bb[3];
            }
#pragma unroll
            for (int mi = 0; mi < 4; mi++)
#pragma unroll
                for (int ni = 0; ni < 4; ni++)
                    mma_f16(acc[mi][ni], af[mi], bf[ni]);
        }
        if (c + 1 < nc) {
            const int nxt = 1 - cur;
            *(uint4*)&As[nxt][arow][akoff] = au0;
            *(uint4*)&As[nxt][arow][akoff + 8] = au1;
            *(uint4*)&Bs[nxt][bkrow][bnoff] = bu0;
            *(uint4*)&Bs[nxt][bkrow][bnoff + 8] = bu1;
        }
        __syncthreads();
    }

#pragma unroll
    for (int mi = 0; mi < 4; mi++) {
#pragma unroll
        for (int ni = 0; ni < 4; ni++) {
            int r = row0 + wm * 64 + mi * 16 + (lane >> 2);
            int cc = col0 + wn * 32 + ni * 8 + (lane & 3) * 2;
            float2 bb = *(const float2*)(bias + cc);
            float2 v0 = make_float2(acc[mi][ni][0] + bb.x, acc[mi][ni][1] + bb.y);
            float2 v1 = make_float2(acc[mi][ni][2] + bb.x, acc[mi][ni][3] + bb.y);
            if (headsplit) {
                int b = r >> 11, s = r & 2047;
                int h = cc >> 6, d = cc & 63;
                float* dst = out + ((size_t)(b * H_ + h) * S_ + s) * DEPTH_ + d;
                *(float2*)dst = v0;
                *(float2*)(dst + 8 * DEPTH_) = v1;
            } else {
                float* dst = out + (size_t)r * D_ + cc;
                *(float2*)dst = v0;
                *(float2*)(dst + 8 * D_) = v1;
            }
        }
    }
}

// Merged Q/K/V projection (grid.z selects projection)
__global__ __launch_bounds__(256, 2) void qkv_kernel(
    const float* __restrict__ q, const float* __restrict__ k, const float* __restrict__ v,
    const float* __restrict__ wq, const float* __restrict__ wk, const float* __restrict__ wv,
    const float* __restrict__ bq, const float* __restrict__ bk, const float* __restrict__ bv,
    float* __restrict__ Qh, float* __restrict__ Kh, float* __restrict__ Vh)
{
    const int z = blockIdx.z;
    const float* X = (z == 0) ? q : (z == 1) ? k : v;
    const float* W = (z == 0) ? wq : (z == 1) ? wk : wv;
    const float* bias = (z == 0) ? bq : (z == 1) ? bk : bv;
    float* out = (z == 0) ? Qh : (z == 1) ? Kh : Vh;
    proj_body(X, W, bias, out, 1);
}

__global__ __launch_bounds__(256, 2) void out_proj_kernel(
    const float* __restrict__ X, const float* __restrict__ W,
    const float* __restrict__ bias, float* __restrict__ out)
{
    proj_body(X, W, bias, out, 0);
}

// ---------------------------------------------------------------------------
// Logits (R7, unchanged): raw logits + per-tile softmax stats.
// ---------------------------------------------------------------------------
__global__ __launch_bounds__(256, 2) void logits_kernel(
    const float* __restrict__ Qh, const float* __restrict__ Kh,
    const float* __restrict__ mask, float* __restrict__ attn,
    float* __restrict__ tm, float* __restrict__ ts)
{
    extern __shared__ float sm[];
    float (*As)[68] = (float(*)[68])sm;
    float (*Bs)[68] = (float(*)[68])(sm + 128 * 68);

    const int bh = blockIdx.z;
    const float* A = Qh + (size_t)bh * S_ * DEPTH_;
    const float* Bm = Kh + (size_t)bh * S_ * DEPTH_;
    float* C = attn + (size_t)bh * S_ * S_;
    const int bidx = bh >> 4;

    const int tid = threadIdx.x, lane = tid & 31, wid = tid >> 5;
    const int wm = wid & 1, wn = wid >> 1;
    const int row0 = blockIdx.y * 128, col0 = blockIdx.x * 128;

#pragma unroll
    for (int t = 0; t < 8; t++) {
        int idx = tid + t * 256;
        int r = idx >> 4, cc = (idx & 15) * 4;
        float4 x = *(const float4*)(A + (size_t)(row0 + r) * DEPTH_ + cc);
        float* d = &As[r][cc];
        d[0] = f2tf(x.x); d[1] = f2tf(x.y); d[2] = f2tf(x.z); d[3] = f2tf(x.w);
        float4 y = *(const float4*)(Bm + (size_t)(col0 + r) * DEPTH_ + cc);
        float* e = &Bs[r][cc];
        e[0] = f2tf(y.x); e[1] = f2tf(y.y); e[2] = f2tf(y.z); e[3] = f2tf(y.w);
    }
    __syncthreads();

    float acc[4][4][4];
#pragma unroll
    for (int mi = 0; mi < 4; mi++)
#pragma unroll
        for (int ni = 0; ni < 4; ni++)
#pragma unroll
            for (int t = 0; t < 4; t++) acc[mi][ni][t] = 0.f;

#pragma unroll
    for (int ks = 0; ks < 8; ks++) {
        unsigned af[4][4], bf[4][2];
#pragma unroll
        for (int mi = 0; mi < 4; mi++) {
            const float* p = &As[wm * 64 + mi * 16 + (lane >> 2)][ks * 8 + (lane & 3)];
            af[mi][0] = U(p[0]); af[mi][1] = U(p[8 * 68]);
            af[mi][2] = U(p[4]); af[mi][3] = U(p[8 * 68 + 4]);
        }
#pragma unroll
        for (int ni = 0; ni < 4; ni++) {
            const float* p = &Bs[wn * 32 + ni * 8 + (lane >> 2)][ks * 8 + (lane & 3)];
            bf[ni][0] = U(p[0]); bf[ni][1] = U(p[4]);
        }
#pragma unroll
        for (int mi = 0; mi < 4; mi++)
#pragma unroll
            for (int ni = 0; ni < 4; ni++)
                mma_tf32(acc[mi][ni][0], acc[mi][ni][1], acc[mi][ni][2], acc[mi][ni][3],
                         af[mi][0], af[mi][1], af[mi][2], af[mi][3],
                         bf[ni][0], bf[ni][1]);
    }

#pragma unroll
    for (int mi = 0; mi < 4; mi++) {
#pragma unroll
        for (int ni = 0; ni < 4; ni++) {
            int q = row0 + wm * 64 + mi * 16 + (lane >> 2);
            int kc = col0 + wn * 32 + ni * 8 + (lane & 3) * 2;
            const float* mrow = mask + ((size_t)bidx * S_ + q) * S_ + kc;
            float2 m0 = *(const float2*)mrow;
            float2 m1 = *(const float2*)(mrow + 8 * S_);
            acc[mi][ni][0] = acc[mi][ni][0] * 0.125f + m0.x * 1e-9f;
            acc[mi][ni][1] = acc[mi][ni][1] * 0.125f + m0.y * 1e-9f;
            acc[mi][ni][2] = acc[mi][ni][2] * 0.125f + m1.x * 1e-9f;
            acc[mi][ni][3] = acc[mi][ni][3] * 0.125f + m1.y * 1e-9f;
            float* dst = C + (size_t)q * S_ + kc;
            *(float2*)dst = make_float2(acc[mi][ni][0], acc[mi][ni][1]);
            *(float2*)(dst + 8 * S_) = make_float2(acc[mi][ni][2], acc[mi][ni][3]);
        }
    }

    __syncthreads();
    float* pm = sm;
    float* Ms = sm + 512;
    float* ps = sm + 768;

#pragma unroll
    for (int mi = 0; mi < 4; mi++) {
#pragma unroll
        for (int h = 0; h < 2; h++) {
            float m = -1e30f;
#pragma unroll
            for (int ni = 0; ni < 4; ni++)
                m = fmaxf(m, fmaxf(acc[mi][ni][2 * h], acc[mi][ni][2 * h + 1]));
            m = fmaxf(m, __shfl_xor_sync(~0u, m, 1));
            m = fmaxf(m, __shfl_xor_sync(~0u, m, 2));
            if ((lane & 3) == 0)
                pm[(wm * 64 + mi * 16 + (lane >> 2) + h * 8) * 4 + wn] = m;
        }
    }
    __syncthreads();
    if (tid < 128)
        Ms[tid] = fmaxf(fmaxf(pm[tid * 4], pm[tid * 4 + 1]),
                        fmaxf(pm[tid * 4 + 2], pm[tid * 4 + 3]));
    __syncthreads();
#pragma unroll
    for (int mi = 0; mi < 4; mi++) {
#pragma unroll
        for (int h = 0; h < 2; h++) {
            int rloc = wm * 64 + mi * 16 + (lane >> 2) + h * 8;
            float M = Ms[rloc];
            float s = 0.f;
#pragma unroll
            for (int ni = 0; ni < 4; ni++)
                s += __expf(acc[mi][ni][2 * h] - M) + __expf(acc[mi][ni][2 * h + 1] - M);
            s += __shfl_xor_sync(~0u, s, 1);
            s += __shfl_xor_sync(~0u, s, 2);
            if ((lane & 3) == 0) ps[rloc * 4 + wn] = s;
        }
    }
    __syncthreads();
    if (tid < 128) {
        float s = ps[tid * 4] + ps[tid * 4 + 1] + ps[tid * 4 + 2] + ps[tid * 4 + 3];
        size_t idx = ((size_t)bh * S_ + row0 + tid) * NT_ + blockIdx.x;
        tm[idx] = Ms[tid];
        ts[idx] = s;
    }
}

// ---------------------------------------------------------------------------
// Row stats (R7, unchanged)
// ---------------------------------------------------------------------------
__global__ __launch_bounds__(256) void rowstats_kernel(
    const float* __restrict__ tm, const float* __restrict__ ts,
    float* __restrict__ rowM, float* __restrict__ rowInv)
{
    int row = blockIdx.x * 256 + threadIdx.x;
    const float4* m4 = (const float4*)(tm + (size_t)row * NT_);
    const float4* s4 = (const float4*)(ts + (size_t)row * NT_);
    float4 ma = m4[0], mb = m4[1], mc = m4[2], md = m4[3];
    float M = fmaxf(fmaxf(fmaxf(ma.x, ma.y), fmaxf(ma.z, ma.w)),
                    fmaxf(fmaxf(fmaxf(mb.x, mb.y), fmaxf(mb.z, mb.w)),
                          fmaxf(fmaxf(fmaxf(mc.x, mc.y), fmaxf(mc.z, mc.w)),
                                fmaxf(fmaxf(md.x, md.y), fmaxf(md.z, md.w)))));
    float4 sa = s4[0], sb = s4[1], sc = s4[2], sd = s4[3];
    float d = sa.x * __expf(ma.x - M) + sa.y * __expf(ma.y - M)
            + sa.z * __expf(ma.z - M) + sa.w * __expf(ma.w - M)
            + sb.x * __expf(mb.x - M) + sb.y * __expf(mb.y - M)
            + sb.z * __expf(mb.z - M) + sb.w * __expf(mb.w - M)
            + sc.x * __expf(mc.x - M) + sc.y * __expf(mc.y - M)
            + sc.z * __expf(mc.z - M) + sc.w * __expf(mc.w - M)
            + sd.x * __expf(md.x - M) + sd.y * __expf(md.y - M)
            + sd.z * __expf(md.z - M) + sd.w * __expf(md.w - M);
    rowM[row] = M;
    rowInv[row] = 1.f / d;
}

// ---------------------------------------------------------------------------
// ctx (R7, unchanged): softmax-applied A fill, normalized writeback, A@V.
// ---------------------------------------------------------------------------
__global__ __launch_bounds__(256, 2) void ctx_kernel(
    float* __restrict__ attn, const float* __restrict__ Vh,
    const float* __restrict__ rowMg, const float* __restrict__ rowInvg,
    float* __restrict__ ctx)
{
    extern __shared__ float sm[];
    float (*As)[128][36] = (float(*)[128][36])sm;
    float (*Bs)[64][36]  = (float(*)[64][36])(sm + 2 * 128 * 36);
    __shared__ float rowM[128], rowInv[128];

    const int bh = blockIdx.y;
    float* A = attn + (size_t)bh * S_ * S_;
    const float* Bm = Vh + (size_t)bh * S_ * DEPTH_;
    const int b = bh >> 4, h = bh & 15;

    const int tid = threadIdx.x, lane = tid & 31, wid = tid >> 5;
    const int wm = wid & 3, wn = wid >> 2;
    const int row0 = blockIdx.x * 128;

    if (tid < 128) {
        rowM[tid] = rowMg[bh * S_ + row0 + tid];
        rowInv[tid] = rowInvg[bh * S_ + row0 + tid];
    }

    float acc[2][4][4];
#pragma unroll
    for (int mi = 0; mi < 2; mi++)
#pragma unroll
        for (int ni = 0; ni < 4; ni++)
#pragma unroll
            for (int t = 0; t < 4; t++) acc[mi][ni][t] = 0.f;

    float4 pa[4], pv[2];
#pragma unroll
    for (int t = 0; t < 4; t++) {
        int idx = tid + t * 256;
        int r = idx >> 3, c0 = (idx & 7) * 4;
        pa[t] = *(const float4*)(A + (size_t)(row0 + r) * S_ + c0);
    }
#pragma unroll
    for (int t = 0; t < 2; t++) {
        int idx = tid + t * 256;
        int kr = idx >> 4, nn = (idx & 15) * 4;
        pv[t] = *(const float4*)(Bm + (size_t)kr * DEPTH_ + nn);
    }
    __syncthreads();

#pragma unroll
    for (int t = 0; t < 4; t++) {
        int idx = tid + t * 256;
        int r = idx >> 3, c0 = (idx & 7) * 4;
        float M = rowM[r], inv = rowInv[r];
        float4 p = make_float4(__expf(pa[t].x - M) * inv, __expf(pa[t].y - M) * inv,
                               __expf(pa[t].z - M) * inv, __expf(pa[t].w - M) * inv);
        *(float4*)(A + (size_t)(row0 + r) * S_ + c0) = p;
        float* d = &As[0][r][c0];
        d[0] = f2tf(p.x); d[1] = f2tf(p.y); d[2] = f2tf(p.z); d[3] = f2tf(p.w);
    }
#pragma unroll
    for (int t = 0; t < 2; t++) {
        int idx = tid + t * 256;
        int kr = idx >> 4, nn = (idx & 15) * 4;
        Bs[0][nn + 0][kr] = f2tf(pv[t].x);
        Bs[0][nn + 1][kr] = f2tf(pv[t].y);
        Bs[0][nn + 2][kr] = f2tf(pv[t].z);
        Bs[0][nn + 3][kr] = f2tf(pv[t].w);
    }
    __syncthreads();

    const int nc = S_ / 32;
    for (int c = 0; c < nc; c++) {
        const int cur = c & 1;
        const int k0n = (c + 1) * 32;
        if (c + 1 < nc) {
#pragma unroll
            for (int t = 0; t < 4; t++) {
                int idx = tid + t * 256;
                int r = idx >> 3, c0 = (idx & 7) * 4;
                pa[t] = *(const float4*)(A + (size_t)(row0 + r) * S_ + k0n + c0);
            }
#pragma unroll
            for (int t = 0; t < 2; t++) {
                int idx = tid + t * 256;
                int kr = idx >> 4, nn = (idx & 15) * 4;
                pv[t] = *(const float4*)(Bm + (size_t)(k0n + kr) * DEPTH_ + nn);
            }
        }
#pragma unroll
        for (int ks = 0; ks < 4; ks++) {
            unsigned af[2][4], bf[4][2];
#pragma unroll
            for (int mi = 0; mi < 2; mi++) {
                const float* p = &As[cur][wm * 32 + mi * 16 + (lane >> 2)][ks * 8 + (lane & 3)];
                af[mi][0] = U(p[0]); af[mi][1] = U(p[8 * 36]);
                af[mi][2] = U(p[4]); af[mi][3] = U(p[8 * 36 + 4]);
            }
#pragma unroll
            for (int ni = 0; ni < 4; ni++) {
                const float* p = &Bs[cur][wn * 32 + ni * 8 + (lane >> 2)][ks * 8 + (lane & 3)];
                bf[ni][0] = U(p[0]); bf[ni][1] = U(p[4]);
            }
#pragma unroll
            for (int mi = 0; mi < 2; mi++)
#pragma unroll
                for (int ni = 0; ni < 4; ni++)
                    mma_tf32(acc[mi][ni][0], acc[mi][ni][1], acc[mi][ni][2], acc[mi][ni][3],
                             af[mi][0], af[mi][1], af[mi][2], af[mi][3],
                             bf[ni][0], bf[ni][1]);
        }
        if (c + 1 < nc) {
            const int nxt = 1 - cur;
#pragma unroll
            for (int t = 0; t < 4; t++) {
                int idx = tid + t * 256;
                int r = idx >> 3, c0 = (idx & 7) * 4;
                float M = rowM[r], inv = rowInv[r];
                float4 p = make_float4(__expf(pa[t].x - M) * inv, __expf(pa[t].y - M) * inv,
                                       __expf(pa[t].z - M) * inv, __expf(pa[t].w - M) * inv);
                *(float4*)(A + (size_t)(row0 + r) * S_ + k0n + c0) = p;
                float* d = &As[nxt][r][c0];
                d[0] = f2tf(p.x); d[1] = f2tf(p.y); d[2] = f2tf(p.z); d[3] = f2tf(p.w);
            }
#pragma unroll
            for (int t = 0; t < 2; t++) {
                int idx = tid + t * 256;
                int kr = idx >> 4, nn = (idx & 15) * 4;
                Bs[nxt][nn + 0][kr] = f2tf(pv[t].x);
                Bs[nxt][nn + 1][kr] = f2tf(pv[t].y);
                Bs[nxt][nn + 2][kr] = f2tf(pv[t].z);
                Bs[nxt][nn + 3][kr] = f2tf(pv[t].w);
            }
        }
        __syncthreads();
    }

#pragma unroll
    for (int mi = 0; mi < 2; mi++) {
#pragma unroll
        for (int ni = 0; ni < 4; ni++) {
            int s = row0 + wm * 32 + mi * 16 + (lane >> 2);
            int cc = wn * 32 + ni * 8 + (lane & 3) * 2;
            float* dst = ctx + ((size_t)(b * S_ + s)) * D_ + h * DEPTH_ + cc;
            *(float2*)dst = make_float2(acc[mi][ni][0], acc[mi][ni][1]);
            *(float2*)(dst + 8 * D_) = make_float2(acc[mi][ni][2], acc[mi][ni][3]);
        }
    }
}

// ---------------------------------------------------------------------------
extern "C" void kernel_launch(void* const* d_in, const int* in_sizes, int n_in,
                              void* d_out, int out_size)
{
    const float* q    = (const float*)d_in[0];
    const float* k    = (const float*)d_in[1];
    const float* v    = (const float*)d_in[2];
    const float* mask = (const float*)d_in[3];
    const float* wq   = (const float*)d_in[4];
    const float* bq   = (const float*)d_in[5];
    const float* wk   = (const float*)d_in[6];
    const float* bk   = (const float*)d_in[7];
    const float* wv   = (const float*)d_in[8];
    const float* bv   = (const float*)d_in[9];
    const float* wo   = (const float*)d_in[10];
    const float* bo   = (const float*)d_in[11];

    float* out = (float*)d_out;

    float* attn;
    if ((size_t)out_size >= (size_t)OUT_ELEMS + ATTN_ELEMS) {
        attn = out + OUT_ELEMS;
    } else {
        cudaGetSymbolAddress((void**)&attn, g_attn_scratch);
    }

    float *Qh, *Kh, *Vh, *ctx, *tm, *ts, *rowM, *rowInv;
    cudaGetSymbolAddress((void**)&Qh, g_Qh);
    cudaGetSymbolAddress((void**)&Kh, g_Kh);
    cudaGetSymbolAddress((void**)&Vh, g_Vh);
    cudaGetSymbolAddress((void**)&ctx, g_ctx);
    cudaGetSymbolAddress((void**)&tm, g_tm);
    cudaGetSymbolAddress((void**)&ts, g_ts);
    cudaGetSymbolAddress((void**)&rowM, g_rowM);
    cudaGetSymbolAddress((void**)&rowInv, g_rowInv);

    const int logitsSmem = 2 * 128 * 68 * sizeof(float);
    const int ctxSmem = (2 * 128 * 36 + 2 * 64 * 36) * sizeof(float);
    cudaFuncSetAttribute(logits_kernel, cudaFuncAttributeMaxDynamicSharedMemorySize, logitsSmem);
    cudaFuncSetAttribute(ctx_kernel, cudaFuncAttributeMaxDynamicSharedMemorySize, ctxSmem);

    dim3 qkvGrid(D_ / 128, M_ / 128, 3);
    qkv_kernel<<<qkvGrid, 256>>>(q, k, v, wq, wk, wv, bq, bk, bv, Qh, Kh, Vh);

    dim3 logitsGrid(S_ / 128, S_ / 128, BH_);
    logits_kernel<<<logitsGrid, 256, logitsSmem>>>(Qh, Kh, mask, attn, tm, ts);

    rowstats_kernel<<<(BH_ * S_) / 256, 256>>>(tm, ts, rowM, rowInv);

    dim3 ctxGrid(S_ / 128, BH_);
    ctx_kernel<<<ctxGrid, 256, ctxSmem>>>(attn, Vh, rowM, rowInv, ctx);

    dim3 projGrid(D_ / 128, M_ / 128);
    out_proj_kernel<<<projGrid, 256>>>(ctx, wo, bo, out);
}

// round 10
// speedup vs baseline: 2.0709x; 1.1162x over previous
#include <cuda_runtime.h>
#include <cuda_fp16.h>
#include <math.h>

// Problem constants
#define B_ 2
#define S_ 2048
#define D_ 1024
#define H_ 16
#define DEPTH_ 64
#define M_ (B_ * S_)            // 4096
#define BH_ (B_ * H_)           // 32
#define NT_ 16                  // 128-col tiles per attn row
#define OUT_ELEMS (B_ * S_ * D_)
#define ATTN_ELEMS ((size_t)BH_ * S_ * S_)

// Scratch (Q/K/V heads now fp16)
__device__ __half g_Qh[(size_t)BH_ * S_ * DEPTH_];
__device__ __half g_Kh[(size_t)BH_ * S_ * DEPTH_];
__device__ __half g_Vh[(size_t)BH_ * S_ * DEPTH_];
__device__ float g_ctx[(size_t)M_ * D_];
__device__ float g_attn_scratch[ATTN_ELEMS];
// Softmax fusion stats
__device__ float g_tm[(size_t)BH_ * S_ * NT_];
__device__ float g_ts[(size_t)BH_ * S_ * NT_];
__device__ float g_rowM[BH_ * S_];
__device__ float g_rowInv[BH_ * S_];

// ---------------------------------------------------------------------------
// fp16 helpers
// ---------------------------------------------------------------------------
__device__ __forceinline__ unsigned h2pack(float a, float b) {
    __half2 h = __floats2half2_rn(a, b);
    return *(unsigned*)&h;
}
__device__ __forceinline__ void ldsm4(unsigned* r, const __half* p) {
    unsigned a = (unsigned)__cvta_generic_to_shared(p);
    asm volatile("ldmatrix.sync.aligned.m8n8.x4.shared.b16 {%0,%1,%2,%3}, [%4];"
                 : "=r"(r[0]), "=r"(r[1]), "=r"(r[2]), "=r"(r[3]) : "r"(a));
}
__device__ __forceinline__ void ldsm4t(unsigned* r, const __half* p) {
    unsigned a = (unsigned)__cvta_generic_to_shared(p);
    asm volatile("ldmatrix.sync.aligned.m8n8.x4.trans.shared.b16 {%0,%1,%2,%3}, [%4];"
                 : "=r"(r[0]), "=r"(r[1]), "=r"(r[2]), "=r"(r[3]) : "r"(a));
}
__device__ __forceinline__ void mma_f16(float* c, const unsigned* a, const unsigned* b) {
    asm volatile(
        "mma.sync.aligned.m16n8k16.row.col.f32.f16.f16.f32 "
        "{%0,%1,%2,%3}, {%4,%5,%6,%7}, {%8,%9}, {%0,%1,%2,%3};"
        : "+f"(c[0]), "+f"(c[1]), "+f"(c[2]), "+f"(c[3])
        : "r"(a[0]), "r"(a[1]), "r"(a[2]), "r"(a[3]), "r"(b[0]), "r"(b[1]));
}

// ---------------------------------------------------------------------------
// Projection GEMM core (R9-proven): CTA 128x128, BK=32 double-buffered,
// 8 warps (2m x 4n). As [m][k] (stride 40), Bs [k][n] (stride 136).
// HALF_OUT=1: head-split fp16 output; else fp32 row-major output.
// ---------------------------------------------------------------------------
template <int HALF_OUT>
__device__ __forceinline__ void proj_body_t(
    const float* __restrict__ X, const float* __restrict__ W,
    const float* __restrict__ bias, float* __restrict__ outf,
    __half* __restrict__ outh)
{
    __shared__ __align__(16) __half As[2][128][40];
    __shared__ __align__(16) __half Bs[2][32][136];
    const int tid = threadIdx.x, lane = tid & 31, wid = tid >> 5;
    const int wm = wid & 1, wn = wid >> 1;
    const int row0 = blockIdx.y * 128, col0 = blockIdx.x * 128;

    const int arow = tid >> 1, akoff = (tid & 1) * 16;
    const int bkrow = tid >> 3, bnoff = (tid & 7) * 16;

    float acc[4][4][4];
#pragma unroll
    for (int mi = 0; mi < 4; mi++)
#pragma unroll
        for (int ni = 0; ni < 4; ni++)
#pragma unroll
            for (int t = 0; t < 4; t++) acc[mi][ni][t] = 0.f;

    uint4 au0, au1, bu0, bu1;
    {
        const float* xp = X + (size_t)(row0 + arow) * D_ + akoff;
        float4 x0 = *(const float4*)xp, x1 = *(const float4*)(xp + 4);
        float4 x2 = *(const float4*)(xp + 8), x3 = *(const float4*)(xp + 12);
        au0 = make_uint4(h2pack(x0.x, x0.y), h2pack(x0.z, x0.w),
                         h2pack(x1.x, x1.y), h2pack(x1.z, x1.w));
        au1 = make_uint4(h2pack(x2.x, x2.y), h2pack(x2.z, x2.w),
                         h2pack(x3.x, x3.y), h2pack(x3.z, x3.w));
        const float* wp = W + (size_t)bkrow * D_ + col0 + bnoff;
        float4 w0 = *(const float4*)wp, w1 = *(const float4*)(wp + 4);
        float4 w2 = *(const float4*)(wp + 8), w3 = *(const float4*)(wp + 12);
        bu0 = make_uint4(h2pack(w0.x, w0.y), h2pack(w0.z, w0.w),
                         h2pack(w1.x, w1.y), h2pack(w1.z, w1.w));
        bu1 = make_uint4(h2pack(w2.x, w2.y), h2pack(w2.z, w2.w),
                         h2pack(w3.x, w3.y), h2pack(w3.z, w3.w));
        *(uint4*)&As[0][arow][akoff] = au0;
        *(uint4*)&As[0][arow][akoff + 8] = au1;
        *(uint4*)&Bs[0][bkrow][bnoff] = bu0;
        *(uint4*)&Bs[0][bkrow][bnoff + 8] = bu1;
    }
    __syncthreads();

    const int nc = D_ / 32;   // 32
    for (int c = 0; c < nc; c++) {
        const int cur = c & 1;
        if (c + 1 < nc) {
            const int k0 = (c + 1) * 32;
            const float* xp = X + (size_t)(row0 + arow) * D_ + k0 + akoff;
            float4 x0 = *(const float4*)xp, x1 = *(const float4*)(xp + 4);
            float4 x2 = *(const float4*)(xp + 8), x3 = *(const float4*)(xp + 12);
            au0 = make_uint4(h2pack(x0.x, x0.y), h2pack(x0.z, x0.w),
                             h2pack(x1.x, x1.y), h2pack(x1.z, x1.w));
            au1 = make_uint4(h2pack(x2.x, x2.y), h2pack(x2.z, x2.w),
                             h2pack(x3.x, x3.y), h2pack(x3.z, x3.w));
            const float* wp = W + (size_t)(k0 + bkrow) * D_ + col0 + bnoff;
            float4 w0 = *(const float4*)wp, w1 = *(const float4*)(wp + 4);
            float4 w2 = *(const float4*)(wp + 8), w3 = *(const float4*)(wp + 12);
            bu0 = make_uint4(h2pack(w0.x, w0.y), h2pack(w0.z, w0.w),
                             h2pack(w1.x, w1.y), h2pack(w1.z, w1.w));
            bu1 = make_uint4(h2pack(w2.x, w2.y), h2pack(w2.z, w2.w),
                             h2pack(w3.x, w3.y), h2pack(w3.z, w3.w));
        }
#pragma unroll
        for (int ks = 0; ks < 2; ks++) {
            const int k = ks * 16;
            unsigned af[4][4], bf[4][2];
#pragma unroll
            for (int mi = 0; mi < 4; mi++) {
                int r = wm * 64 + mi * 16 + (lane & 15);
                ldsm4(af[mi], &As[cur][r][k + ((lane >> 4) << 3)]);
            }
#pragma unroll
            for (int np = 0; np < 2; np++) {
                unsigned bb[4];
                int kr = k + (lane & 7) + ((lane >> 3) & 1) * 8;
                int nn = wn * 32 + np * 16 + (lane >> 4) * 8;
                ldsm4t(bb, &Bs[cur][kr][nn]);
                bf[np * 2 + 0][0] = bb[0]; bf[np * 2 + 0][1] = bb[1];
                bf[np * 2 + 1][0] = bb[2]; bf[np * 2 + 1][1] = bb[3];
            }
#pragma unroll
            for (int mi = 0; mi < 4; mi++)
#pragma unroll
                for (int ni = 0; ni < 4; ni++)
                    mma_f16(acc[mi][ni], af[mi], bf[ni]);
        }
        if (c + 1 < nc) {
            const int nxt = 1 - cur;
            *(uint4*)&As[nxt][arow][akoff] = au0;
            *(uint4*)&As[nxt][arow][akoff + 8] = au1;
            *(uint4*)&Bs[nxt][bkrow][bnoff] = bu0;
            *(uint4*)&Bs[nxt][bkrow][bnoff + 8] = bu1;
        }
        __syncthreads();
    }

#pragma unroll
    for (int mi = 0; mi < 4; mi++) {
#pragma unroll
        for (int ni = 0; ni < 4; ni++) {
            int r = row0 + wm * 64 + mi * 16 + (lane >> 2);
            int cc = col0 + wn * 32 + ni * 8 + (lane & 3) * 2;
            float2 bb = *(const float2*)(bias + cc);
            float2 v0 = make_float2(acc[mi][ni][0] + bb.x, acc[mi][ni][1] + bb.y);
            float2 v1 = make_float2(acc[mi][ni][2] + bb.x, acc[mi][ni][3] + bb.y);
            if (HALF_OUT) {
                int b = r >> 11, s = r & 2047;
                int h = cc >> 6, d = cc & 63;
                __half* dst = outh + ((size_t)(b * H_ + h) * S_ + s) * DEPTH_ + d;
                *(unsigned*)dst = h2pack(v0.x, v0.y);
                *(unsigned*)(dst + 8 * DEPTH_) = h2pack(v1.x, v1.y);
            } else {
                float* dst = outf + (size_t)r * D_ + cc;
                *(float2*)dst = v0;
                *(float2*)(dst + 8 * D_) = v1;
            }
        }
    }
}

// Merged Q/K/V projection (grid.z selects projection), fp16 head-split out
__global__ __launch_bounds__(256, 2) void qkv_kernel(
    const float* __restrict__ q, const float* __restrict__ k, const float* __restrict__ v,
    const float* __restrict__ wq, const float* __restrict__ wk, const float* __restrict__ wv,
    const float* __restrict__ bq, const float* __restrict__ bk, const float* __restrict__ bv,
    __half* __restrict__ Qh, __half* __restrict__ Kh, __half* __restrict__ Vh)
{
    const int z = blockIdx.z;
    const float* X = (z == 0) ? q : (z == 1) ? k : v;
    const float* W = (z == 0) ? wq : (z == 1) ? wk : wv;
    const float* bias = (z == 0) ? bq : (z == 1) ? bk : bv;
    __half* out = (z == 0) ? Qh : (z == 1) ? Kh : Vh;
    proj_body_t<1>(X, W, bias, nullptr, out);
}

__global__ __launch_bounds__(256, 2) void out_proj_kernel(
    const float* __restrict__ X, const float* __restrict__ W,
    const float* __restrict__ bias, float* __restrict__ out)
{
    proj_body_t<0>(X, W, bias, out, nullptr);
}

// ---------------------------------------------------------------------------
// Logits: C = Qh @ Kh^T * 0.125 + mask*1e-9 (raw) + per-tile softmax stats.
// fp16 mma m16n8k16; Q,K tiles [128][64] halfs (stride 72), non-trans LDSM
// for both operands (both are k-contiguous). K=64 = 4 ksteps, staged once.
// Dynamic smem: 2 * 128 * 72 halfs = 36864 B.
// ---------------------------------------------------------------------------
__global__ __launch_bounds__(256, 2) void logits_kernel(
    const __half* __restrict__ Qh, const __half* __restrict__ Kh,
    const float* __restrict__ mask, float* __restrict__ attn,
    float* __restrict__ tm, float* __restrict__ ts)
{
    extern __shared__ char smraw[];
    __half (*As)[72] = (__half(*)[72])smraw;
    __half (*Bs)[72] = (__half(*)[72])(smraw + 128 * 72 * 2);

    const int bh = blockIdx.z;
    const __half* A = Qh + (size_t)bh * S_ * DEPTH_;
    const __half* Bm = Kh + (size_t)bh * S_ * DEPTH_;
    float* C = attn + (size_t)bh * S_ * S_;
    const int bidx = bh >> 4;

    const int tid = threadIdx.x, lane = tid & 31, wid = tid >> 5;
    const int wm = wid & 1, wn = wid >> 1;
    const int row0 = blockIdx.y * 128, col0 = blockIdx.x * 128;

    // Fill both tiles: 8 halfs (uint4) per thread per pass, 4 passes each
#pragma unroll
    for (int t = 0; t < 4; t++) {
        int idx = tid + t * 256;
        int r = idx >> 3, c8 = (idx & 7) * 8;
        *(uint4*)&As[r][c8] = *(const uint4*)(A + (size_t)(row0 + r) * DEPTH_ + c8);
        *(uint4*)&Bs[r][c8] = *(const uint4*)(Bm + (size_t)(col0 + r) * DEPTH_ + c8);
    }
    __syncthreads();

    float acc[4][4][4];
#pragma unroll
    for (int mi = 0; mi < 4; mi++)
#pragma unroll
        for (int ni = 0; ni < 4; ni++)
#pragma unroll
            for (int t = 0; t < 4; t++) acc[mi][ni][t] = 0.f;

#pragma unroll
    for (int ks = 0; ks < 4; ks++) {
        const int k = ks * 16;
        unsigned af[4][4], bf[4][2];
#pragma unroll
        for (int mi = 0; mi < 4; mi++) {
            int r = wm * 64 + mi * 16 + (lane & 15);
            ldsm4(af[mi], &As[r][k + ((lane >> 4) << 3)]);
        }
#pragma unroll
        for (int np = 0; np < 2; np++) {
            unsigned bb[4];
            int rr = wn * 32 + np * 16 + (lane & 7) + ((lane >> 3) & 1) * 8;
            int cc = k + (lane >> 4) * 8;
            ldsm4(bb, &Bs[rr][cc]);
            bf[np * 2 + 0][0] = bb[0]; bf[np * 2 + 0][1] = bb[2];
            bf[np * 2 + 1][0] = bb[1]; bf[np * 2 + 1][1] = bb[3];
        }
#pragma unroll
        for (int mi = 0; mi < 4; mi++)
#pragma unroll
            for (int ni = 0; ni < 4; ni++)
                mma_f16(acc[mi][ni], af[mi], bf[ni]);
    }

    // Epilogue: scale + mask, write raw logits
#pragma unroll
    for (int mi = 0; mi < 4; mi++) {
#pragma unroll
        for (int ni = 0; ni < 4; ni++) {
            int q = row0 + wm * 64 + mi * 16 + (lane >> 2);
            int kc = col0 + wn * 32 + ni * 8 + (lane & 3) * 2;
            const float* mrow = mask + ((size_t)bidx * S_ + q) * S_ + kc;
            float2 m0 = *(const float2*)mrow;
            float2 m1 = *(const float2*)(mrow + 8 * S_);
            acc[mi][ni][0] = acc[mi][ni][0] * 0.125f + m0.x * 1e-9f;
            acc[mi][ni][1] = acc[mi][ni][1] * 0.125f + m0.y * 1e-9f;
            acc[mi][ni][2] = acc[mi][ni][2] * 0.125f + m1.x * 1e-9f;
            acc[mi][ni][3] = acc[mi][ni][3] * 0.125f + m1.y * 1e-9f;
            float* dst = C + (size_t)q * S_ + kc;
            *(float2*)dst = make_float2(acc[mi][ni][0], acc[mi][ni][1]);
            *(float2*)(dst + 8 * S_) = make_float2(acc[mi][ni][2], acc[mi][ni][3]);
        }
    }

    // Tile softmax stats (reuse smem as float scratch)
    __syncthreads();
    float* smf = (float*)smraw;
    float* pm = smf;           // [128][4]
    float* Ms = smf + 512;     // [128]
    float* ps = smf + 768;     // [128][4]

#pragma unroll
    for (int mi = 0; mi < 4; mi++) {
#pragma unroll
        for (int h = 0; h < 2; h++) {
            float m = -1e30f;
#pragma unroll
            for (int ni = 0; ni < 4; ni++)
                m = fmaxf(m, fmaxf(acc[mi][ni][2 * h], acc[mi][ni][2 * h + 1]));
            m = fmaxf(m, __shfl_xor_sync(~0u, m, 1));
            m = fmaxf(m, __shfl_xor_sync(~0u, m, 2));
            if ((lane & 3) == 0)
                pm[(wm * 64 + mi * 16 + (lane >> 2) + h * 8) * 4 + wn] = m;
        }
    }
    __syncthreads();
    if (tid < 128)
        Ms[tid] = fmaxf(fmaxf(pm[tid * 4], pm[tid * 4 + 1]),
                        fmaxf(pm[tid * 4 + 2], pm[tid * 4 + 3]));
    __syncthreads();
#pragma unroll
    for (int mi = 0; mi < 4; mi++) {
#pragma unroll
        for (int h = 0; h < 2; h++) {
            int rloc = wm * 64 + mi * 16 + (lane >> 2) + h * 8;
            float M = Ms[rloc];
            float s = 0.f;
#pragma unroll
            for (int ni = 0; ni < 4; ni++)
                s += __expf(acc[mi][ni][2 * h] - M) + __expf(acc[mi][ni][2 * h + 1] - M);
            s += __shfl_xor_sync(~0u, s, 1);
            s += __shfl_xor_sync(~0u, s, 2);
            if ((lane & 3) == 0) ps[rloc * 4 + wn] = s;
        }
    }
    __syncthreads();
    if (tid < 128) {
        float s = ps[tid * 4] + ps[tid * 4 + 1] + ps[tid * 4 + 2] + ps[tid * 4 + 3];
        size_t idx = ((size_t)bh * S_ + row0 + tid) * NT_ + blockIdx.x;
        tm[idx] = Ms[tid];
        ts[idx] = s;
    }
}

// ---------------------------------------------------------------------------
// Row stats (unchanged)
// ---------------------------------------------------------------------------
__global__ __launch_bounds__(256) void rowstats_kernel(
    const float* __restrict__ tm, const float* __restrict__ ts,
    float* __restrict__ rowM, float* __restrict__ rowInv)
{
    int row = blockIdx.x * 256 + threadIdx.x;
    const float4* m4 = (const float4*)(tm + (size_t)row * NT_);
    const float4* s4 = (const float4*)(ts + (size_t)row * NT_);
    float4 ma = m4[0], mb = m4[1], mc = m4[2], md = m4[3];
    float M = fmaxf(fmaxf(fmaxf(ma.x, ma.y), fmaxf(ma.z, ma.w)),
                    fmaxf(fmaxf(fmaxf(mb.x, mb.y), fmaxf(mb.z, mb.w)),
                          fmaxf(fmaxf(fmaxf(mc.x, mc.y), fmaxf(mc.z, mc.w)),
                                fmaxf(fmaxf(md.x, md.y), fmaxf(md.z, md.w)))));
    float4 sa = s4[0], sb = s4[1], sc = s4[2], sd = s4[3];
    float d = sa.x * __expf(ma.x - M) + sa.y * __expf(ma.y - M)
            + sa.z * __expf(ma.z - M) + sa.w * __expf(ma.w - M)
            + sb.x * __expf(mb.x - M) + sb.y * __expf(mb.y - M)
            + sb.z * __expf(mb.z - M) + sb.w * __expf(mb.w - M)
            + sc.x * __expf(mc.x - M) + sc.y * __expf(mc.y - M)
            + sc.z * __expf(mc.z - M) + sc.w * __expf(mc.w - M)
            + sd.x * __expf(md.x - M) + sd.y * __expf(md.y - M)
            + sd.z * __expf(md.z - M) + sd.w * __expf(md.w - M);
    rowM[row] = M;
    rowInv[row] = 1.f / d;
}

// ---------------------------------------------------------------------------
// ctx = softmax(attn_raw) @ Vh; writes normalized probs back to attn (fp32).
// fp16 mma. CTA 128m x 64n, BK=32 double-buffered, 8 warps (4m x 2n).
// As [2][128][40] halfs, Bs [2][32][72] halfs.
// Dynamic smem: 20480 + 9216 = 29696 B.
// ---------------------------------------------------------------------------
__global__ __launch_bounds__(256, 2) void ctx_kernel(
    float* __restrict__ attn, const __half* __restrict__ Vh,
    const float* __restrict__ rowMg, const float* __restrict__ rowInvg,
    float* __restrict__ ctx)
{
    extern __shared__ char smraw[];
    __half (*As)[128][40] = (__half(*)[128][40])smraw;
    __half (*Bs)[32][72]  = (__half(*)[32][72])(smraw + 2 * 128 * 40 * 2);
    __shared__ float rowM[128], rowInv[128];

    const int bh = blockIdx.y;
    float* A = attn + (size_t)bh * S_ * S_;
    const __half* Bm = Vh + (size_t)bh * S_ * DEPTH_;
    const int b = bh >> 4, h = bh & 15;

    const int tid = threadIdx.x, lane = tid & 31, wid = tid >> 5;
    const int wm = wid & 3, wn = wid >> 2;
    const int row0 = blockIdx.x * 128;

    if (tid < 128) {
        rowM[tid] = rowMg[bh * S_ + row0 + tid];
        rowInv[tid] = rowInvg[bh * S_ + row0 + tid];
    }

    float acc[2][4][4];
#pragma unroll
    for (int mi = 0; mi < 2; mi++)
#pragma unroll
        for (int ni = 0; ni < 4; ni++)
#pragma unroll
            for (int t = 0; t < 4; t++) acc[mi][ni][t] = 0.f;

    const int vkr = tid >> 3, vno = (tid & 7) * 8;   // V fill: uint4 per thread

    float4 pa[4];
    uint4 pv;
#pragma unroll
    for (int t = 0; t < 4; t++) {
        int idx = tid + t * 256;
        int r = idx >> 3, c0 = (idx & 7) * 4;
        pa[t] = *(const float4*)(A + (size_t)(row0 + r) * S_ + c0);
    }
    pv = *(const uint4*)(Bm + (size_t)vkr * DEPTH_ + vno);
    __syncthreads();   // rowM/rowInv ready

#pragma unroll
    for (int t = 0; t < 4; t++) {
        int idx = tid + t * 256;
        int r = idx >> 3, c0 = (idx & 7) * 4;
        float M = rowM[r], inv = rowInv[r];
        float4 p = make_float4(__expf(pa[t].x - M) * inv, __expf(pa[t].y - M) * inv,
                               __expf(pa[t].z - M) * inv, __expf(pa[t].w - M) * inv);
        *(float4*)(A + (size_t)(row0 + r) * S_ + c0) = p;
        *(uint2*)&As[0][r][c0] = make_uint2(h2pack(p.x, p.y), h2pack(p.z, p.w));
    }
    *(uint4*)&Bs[0][vkr][vno] = pv;
    __syncthreads();

    const int nc = S_ / 32;   // 64
    for (int c = 0; c < nc; c++) {
        const int cur = c & 1;
        const int k0n = (c + 1) * 32;
        if (c + 1 < nc) {
#pragma unroll
            for (int t = 0; t < 4; t++) {
                int idx = tid + t * 256;
                int r = idx >> 3, c0 = (idx & 7) * 4;
                pa[t] = *(const float4*)(A + (size_t)(row0 + r) * S_ + k0n + c0);
            }
            pv = *(const uint4*)(Bm + (size_t)(k0n + vkr) * DEPTH_ + vno);
        }
#pragma unroll
        for (int ks = 0; ks < 2; ks++) {
            const int k = ks * 16;
            unsigned af[2][4], bf[4][2];
#pragma unroll
            for (int mi = 0; mi < 2; mi++) {
                int r = wm * 32 + mi * 16 + (lane & 15);
                ldsm4(af[mi], &As[cur][r][k + ((lane >> 4) << 3)]);
            }
#pragma unroll
            for (int np = 0; np < 2; np++) {
                unsigned bb[4];
                int kr = k + (lane & 7) + ((lane >> 3) & 1) * 8;
                int nn = wn * 32 + np * 16 + (lane >> 4) * 8;
                ldsm4t(bb, &Bs[cur][kr][nn]);
                bf[np * 2 + 0][0] = bb[0]; bf[np * 2 + 0][1] = bb[1];
                bf[np * 2 + 1][0] = bb[2]; bf[np * 2 + 1][1] = bb[3];
            }
#pragma unroll
            for (int mi = 0; mi < 2; mi++)
#pragma unroll
                for (int ni = 0; ni < 4; ni++)
                    mma_f16(acc[mi][ni], af[mi], bf[ni]);
        }
        if (c + 1 < nc) {
            const int nxt = 1 - cur;
#pragma unroll
            for (int t = 0; t < 4; t++) {
                int idx = tid + t * 256;
                int r = idx >> 3, c0 = (idx & 7) * 4;
                float M = rowM[r], inv = rowInv[r];
                float4 p = make_float4(__expf(pa[t].x - M) * inv, __expf(pa[t].y - M) * inv,
                                       __expf(pa[t].z - M) * inv, __expf(pa[t].w - M) * inv);
                *(float4*)(A + (size_t)(row0 + r) * S_ + k0n + c0) = p;
                *(uint2*)&As[nxt][r][c0] = make_uint2(h2pack(p.x, p.y), h2pack(p.z, p.w));
            }
            *(uint4*)&Bs[nxt][vkr][vno] = pv;
        }
        __syncthreads();
    }

#pragma unroll
    for (int mi = 0; mi < 2; mi++) {
#pragma unroll
        for (int ni = 0; ni < 4; ni++) {
            int s = row0 + wm * 32 + mi * 16 + (lane >> 2);
            int cc = wn * 32 + ni * 8 + (lane & 3) * 2;
            float* dst = ctx + ((size_t)(b * S_ + s)) * D_ + h * DEPTH_ + cc;
            *(float2*)dst = make_float2(acc[mi][ni][0], acc[mi][ni][1]);
            *(float2*)(dst + 8 * D_) = make_float2(acc[mi][ni][2], acc[mi][ni][3]);
        }
    }
}

// ---------------------------------------------------------------------------
extern "C" void kernel_launch(void* const* d_in, const int* in_sizes, int n_in,
                              void* d_out, int out_size)
{
    const float* q    = (const float*)d_in[0];
    const float* k    = (const float*)d_in[1];
    const float* v    = (const float*)d_in[2];
    const float* mask = (const float*)d_in[3];
    const float* wq   = (const float*)d_in[4];
    const float* bq   = (const float*)d_in[5];
    const float* wk   = (const float*)d_in[6];
    const float* bk   = (const float*)d_in[7];
    const float* wv   = (const float*)d_in[8];
    const float* bv   = (const float*)d_in[9];
    const float* wo   = (const float*)d_in[10];
    const float* bo   = (const float*)d_in[11];

    float* out = (float*)d_out;

    float* attn;
    if ((size_t)out_size >= (size_t)OUT_ELEMS + ATTN_ELEMS) {
        attn = out + OUT_ELEMS;
    } else {
        cudaGetSymbolAddress((void**)&attn, g_attn_scratch);
    }

    __half *Qh, *Kh, *Vh;
    float *ctx, *tm, *ts, *rowM, *rowInv;
    cudaGetSymbolAddress((void**)&Qh, g_Qh);
    cudaGetSymbolAddress((void**)&Kh, g_Kh);
    cudaGetSymbolAddress((void**)&Vh, g_Vh);
    cudaGetSymbolAddress((void**)&ctx, g_ctx);
    cudaGetSymbolAddress((void**)&tm, g_tm);
    cudaGetSymbolAddress((void**)&ts, g_ts);
    cudaGetSymbolAddress((void**)&rowM, g_rowM);
    cudaGetSymbolAddress((void**)&rowInv, g_rowInv);

    const int logitsSmem = 2 * 128 * 72 * 2;             // 36864 B
    const int ctxSmem = 2 * 128 * 40 * 2 + 2 * 32 * 72 * 2;  // 29696 B
    cudaFuncSetAttribute(logits_kernel, cudaFuncAttributeMaxDynamicSharedMemorySize, logitsSmem);
    cudaFuncSetAttribute(ctx_kernel, cudaFuncAttributeMaxDynamicSharedMemorySize, ctxSmem);

    dim3 qkvGrid(D_ / 128, M_ / 128, 3);
    qkv_kernel<<<qkvGrid, 256>>>(q, k, v, wq, wk, wv, bq, bk, bv, Qh, Kh, Vh);

    dim3 logitsGrid(S_ / 128, S_ / 128, BH_);
    logits_kernel<<<logitsGrid, 256, logitsSmem>>>(Qh, Kh, mask, attn, tm, ts);

    rowstats_kernel<<<(BH_ * S_) / 256, 256>>>(tm, ts, rowM, rowInv);

    dim3 ctxGrid(S_ / 128, BH_);
    ctx_kernel<<<ctxGrid, 256, ctxSmem>>>(attn, Vh, rowM, rowInv, ctx);

    dim3 projGrid(D_ / 128, M_ / 128);
    out_proj_kernel<<<projGrid, 256>>>(ctx, wo, bo, out);
}